// round 6
// baseline (speedup 1.0000x reference)
#include <cuda_runtime.h>
#include <math.h>

// ---------------- static workspace (no allocations allowed) ----------------
#define CHUNKS 256
__device__ float g_x0[25165824];   // max N*Bt*Fin = 768*256*128
__device__ float g_x1[25165824];
__device__ float g_x2[25165824];
__device__ float g_y [12582912];   // max conv output = 768*256*64
__device__ float g_s3[12582912];   // 768*256*64
__device__ float g_s2[ 6291456];   // 192*256*128
__device__ float g_s1[ 3145728];   // 48*256*256
__device__ float g_part[CHUNKS * 512];
__device__ float g_bnp[512];       // [0..F) scale, [F..2F) shift

// ---------------- generic SGEMM: C = alpha * A@B + beta * D ----------------
// A: MxK row-major, B: KxN row-major, C/D: MxN row-major. D may be null (beta=0)
#define BM 128
#define BN 128
#define BKK 8

__global__ __launch_bounds__(256) void sgemm_k(
    const float* __restrict__ A, const float* __restrict__ B,
    const float* __restrict__ D, float* __restrict__ C,
    int M, int N, int K, float alpha, float beta)
{
    __shared__ float As[BKK][BM + 4];   // transposed A tile, padded
    __shared__ float Bs[BKK][BN];

    int tid = threadIdx.x;
    int tx = tid & 15, ty = tid >> 4;
    int m0 = blockIdx.y * BM, n0 = blockIdx.x * BN;

    float acc[8][8];
#pragma unroll
    for (int i = 0; i < 8; i++)
#pragma unroll
        for (int j = 0; j < 8; j++) acc[i][j] = 0.0f;

    int arow = tid >> 1;          // 0..127
    int acol = (tid & 1) * 4;     // 0 or 4
    int brow = tid >> 5;          // 0..7
    int bcol = (tid & 31) * 4;    // 0..124

    for (int k0 = 0; k0 < K; k0 += BKK) {
        // --- load A tile (transposed into smem) ---
        float4 av = make_float4(0.f, 0.f, 0.f, 0.f);
        int ga_r = m0 + arow;
        int ga_c = k0 + acol;
        if (ga_r < M) {
            const float* p = A + (size_t)ga_r * K;
            if (ga_c + 3 < K) {
                av = *(const float4*)(p + ga_c);
            } else {
                if (ga_c + 0 < K) av.x = p[ga_c + 0];
                if (ga_c + 1 < K) av.y = p[ga_c + 1];
                if (ga_c + 2 < K) av.z = p[ga_c + 2];
                if (ga_c + 3 < K) av.w = p[ga_c + 3];
            }
        }
        As[acol + 0][arow] = av.x;
        As[acol + 1][arow] = av.y;
        As[acol + 2][arow] = av.z;
        As[acol + 3][arow] = av.w;

        // --- load B tile ---
        float4 bv = make_float4(0.f, 0.f, 0.f, 0.f);
        int gb_r = k0 + brow;
        int gb_c = n0 + bcol;
        if (gb_r < K) {
            const float* p = B + (size_t)gb_r * N;
            if (gb_c + 3 < N) {
                bv = *(const float4*)(p + gb_c);
            } else {
                if (gb_c + 0 < N) bv.x = p[gb_c + 0];
                if (gb_c + 1 < N) bv.y = p[gb_c + 1];
                if (gb_c + 2 < N) bv.z = p[gb_c + 2];
                if (gb_c + 3 < N) bv.w = p[gb_c + 3];
            }
        }
        *(float4*)&Bs[brow][bcol] = bv;
        __syncthreads();

#pragma unroll
        for (int kk = 0; kk < BKK; kk++) {
            float a[8], b[8];
            *(float4*)&a[0] = *(const float4*)&As[kk][ty * 8];
            *(float4*)&a[4] = *(const float4*)&As[kk][ty * 8 + 4];
            *(float4*)&b[0] = *(const float4*)&Bs[kk][tx * 8];
            *(float4*)&b[4] = *(const float4*)&Bs[kk][tx * 8 + 4];
#pragma unroll
            for (int i = 0; i < 8; i++)
#pragma unroll
                for (int j = 0; j < 8; j++) acc[i][j] += a[i] * b[j];
        }
        __syncthreads();
    }

    // --- epilogue ---
#pragma unroll
    for (int i = 0; i < 8; i++) {
        int r = m0 + ty * 8 + i;
        if (r < M) {
            size_t ro = (size_t)r * N;
#pragma unroll
            for (int j = 0; j < 8; j++) {
                int c = n0 + tx * 8 + j;
                if (c < N) {
                    float v = alpha * acc[i][j];
                    if (beta != 0.0f) v += beta * D[ro + c];
                    C[ro + c] = v;
                }
            }
        }
    }
}

// ---------------- elementwise / reduction kernels ----------------

// dst[(n*256+bt)*8+c] = x[b,c,hw,n] with bt = b*64+hw ; x: (4,8,64,768)
__global__ __launch_bounds__(256) void k_transpose_in(const float* __restrict__ x,
                                                      float* __restrict__ dst, int total)
{
    int i = blockIdx.x * blockDim.x + threadIdx.x;
    if (i >= total) return;
    int c  = i & 7;
    int bt = (i >> 3) & 255;
    int n  = i >> 11;
    int b  = bt >> 6, hw = bt & 63;
    dst[i] = x[(((b << 3) + c) * 64 + hw) * 768 + n];
}

// per-chunk partial sums/sumsqs per channel (deterministic)
__global__ __launch_bounds__(256) void k_bn_partial(const float* __restrict__ Y,
                                                    int rows, int F, float* __restrict__ part)
{
    __shared__ float sh[512];
    int blk = blockIdx.x;
    int rpc = (rows + CHUNKS - 1) / CHUNKS;
    int r0 = blk * rpc;
    int r1 = rows < r0 + rpc ? rows : r0 + rpc;
    int tid = threadIdx.x;
    int c = tid % F;
    int g = tid / F;
    int GP = blockDim.x / F;
    float s = 0.f, q = 0.f;
    for (int r = r0 + g; r < r1; r += GP) {
        float v = Y[(size_t)r * F + c];
        s += v; q += v * v;
    }
    sh[tid] = s;
    sh[256 + tid] = q;
    __syncthreads();
    if (g == 0) {
        for (int gg = 1; gg < GP; gg++) {
            s += sh[gg * F + c];
            q += sh[256 + gg * F + c];
        }
        part[blk * 2 * F + c] = s;
        part[blk * 2 * F + F + c] = q;
    }
}

__global__ __launch_bounds__(256) void k_bn_final(const float* __restrict__ part, int F, float cnt,
                                                  const float* __restrict__ gam,
                                                  const float* __restrict__ bet,
                                                  float* __restrict__ bn)
{
    int c = threadIdx.x;
    if (c >= F) return;
    float s = 0.f, q = 0.f;
    for (int ch = 0; ch < CHUNKS; ch++) {
        s += part[ch * 2 * F + c];
        q += part[ch * 2 * F + F + c];
    }
    float mean = s / cnt;
    float var = q / cnt - mean * mean;
    float sc = gam[c] * rsqrtf(var + 1e-5f);
    bn[c] = sc;
    bn[F + c] = bet[c] - mean * sc;
}

__global__ __launch_bounds__(256) void k_bn_apply(const float* __restrict__ Y,
                                                  const float* __restrict__ bn,
                                                  float* __restrict__ dst, int total, int F)
{
    int i = blockIdx.x * blockDim.x + threadIdx.x;
    if (i >= total) return;
    int c = i % F;
    float v = Y[i] * bn[c] + bn[F + c];
    dst[i] = v > 0.f ? v : 0.f;
}

// bn + relu + 4:1 max-pool over node dim (node-major layout)
__global__ __launch_bounds__(256) void k_bn_pool(const float* __restrict__ Y,
                                                 const float* __restrict__ bn,
                                                 float* __restrict__ dst,
                                                 int total /*Nout*Bt*F*/, int F, int BtF)
{
    int i = blockIdx.x * blockDim.x + threadIdx.x;
    if (i >= total) return;
    int c = i % F;
    int inner = i % BtF;
    int j = i / BtF;
    float sc = bn[c], sh = bn[F + c];
    size_t base = (size_t)(4 * j) * BtF + inner;
    float m = Y[base] * sc + sh;
#pragma unroll
    for (int q = 1; q < 4; q++) {
        float v = Y[base + (size_t)q * BtF] * sc + sh;
        if (v > m) m = v;
    }
    dst[i] = m > 0.f ? m : 0.f;
}

// bn + relu + 1:4 unpool, written into concat buffer columns [0, F1)
__global__ __launch_bounds__(256) void k_bn_unpool_cat(const float* __restrict__ Y,
                                                       const float* __restrict__ bn,
                                                       float* __restrict__ dst,
                                                       int total /*N*Bt*F1*/, int F1, int Ftot, int Bt)
{
    int i = blockIdx.x * blockDim.x + threadIdx.x;
    if (i >= total) return;
    int f = i % F1;
    int r = i / F1;          // r = n*Bt + bt
    int bt = r % Bt;
    int n = r / Bt;
    int j = n >> 2;
    float v = Y[((size_t)j * Bt + bt) * F1 + f] * bn[f] + bn[F1 + f];
    dst[(size_t)r * Ftot + f] = v > 0.f ? v : 0.f;
}

// copy skip into concat buffer columns [off, off+Fs)
__global__ __launch_bounds__(256) void k_copy_cat(const float* __restrict__ S,
                                                  float* __restrict__ dst,
                                                  int total /*rows*Fs*/, int Fs, int Ftot, int off)
{
    int i = blockIdx.x * blockDim.x + threadIdx.x;
    if (i >= total) return;
    int f = i % Fs;
    int r = i / Fs;
    dst[(size_t)r * Ftot + off + f] = S[i];
}

// out[bt*768 + n] = Y[n*256 + bt]
__global__ __launch_bounds__(256) void k_transpose_out(const float* __restrict__ Y,
                                                       float* __restrict__ out)
{
    int i = blockIdx.x * blockDim.x + threadIdx.x;
    if (i >= 196608) return;
    int n = i % 768, bt = i / 768;
    out[i] = Y[n * 256 + bt];
}

// ---------------- host orchestration ----------------
static inline void gemm(const float* A, const float* B, const float* D, float* C,
                        int M, int N, int K, float alpha, float beta)
{
    dim3 grid((N + BN - 1) / BN, (M + BM - 1) / BM);
    sgemm_k<<<grid, 256>>>(A, B, D, C, M, N, K, alpha, beta);
}

extern "C" void kernel_launch(void* const* d_in, const int* in_sizes, int n_in,
                              void* d_out, int out_size)
{
    const float* x    = (const float*)d_in[0];
    const float* L3   = (const float*)d_in[1];
    const float* L2   = (const float*)d_in[2];
    const float* L1   = (const float*)d_in[3];
    const float* L0   = (const float*)d_in[4];
    const float* w_e3a = (const float*)d_in[5];
    const float* g_e3a = (const float*)d_in[6];
    const float* b_e3a = (const float*)d_in[7];
    const float* w_e3b = (const float*)d_in[8];
    const float* g_e3b = (const float*)d_in[9];
    const float* b_e3b = (const float*)d_in[10];
    const float* w_e2  = (const float*)d_in[11];
    const float* g_e2  = (const float*)d_in[12];
    const float* b_e2  = (const float*)d_in[13];
    const float* w_e1  = (const float*)d_in[14];
    const float* g_e1  = (const float*)d_in[15];
    const float* b_e1  = (const float*)d_in[16];
    const float* w_e0  = (const float*)d_in[17];
    const float* g_e0  = (const float*)d_in[18];
    const float* b_e0  = (const float*)d_in[19];
    const float* w_d1  = (const float*)d_in[20];
    const float* g_d1  = (const float*)d_in[21];
    const float* b_d1  = (const float*)d_in[22];
    const float* w_d2  = (const float*)d_in[23];
    const float* g_d2  = (const float*)d_in[24];
    const float* b_d2  = (const float*)d_in[25];
    const float* w_d3  = (const float*)d_in[26];
    const float* g_d3  = (const float*)d_in[27];
    const float* b_d3  = (const float*)d_in[28];
    const float* w_out = (const float*)d_in[29];
    float* out = (float*)d_out;

    float *X0, *X1, *X2, *Yb, *S3, *S2, *S1, *Pt, *BNp;
    cudaGetSymbolAddress((void**)&X0, g_x0);
    cudaGetSymbolAddress((void**)&X1, g_x1);
    cudaGetSymbolAddress((void**)&X2, g_x2);
    cudaGetSymbolAddress((void**)&Yb, g_y);
    cudaGetSymbolAddress((void**)&S3, g_s3);
    cudaGetSymbolAddress((void**)&S2, g_s2);
    cudaGetSymbolAddress((void**)&S1, g_s1);
    cudaGetSymbolAddress((void**)&Pt, g_part);
    cudaGetSymbolAddress((void**)&BNp, g_bnp);

    const int Bt = 256;

    auto cheb = [&](const float* L, int Nn, int Fin, int Fout, const float* w) {
        int rows = Nn * Bt;
        int cols = Bt * Fin;
        // Y = X0 @ w0
        gemm(X0, w, nullptr, Yb, rows, Fout, Fin, 1.f, 0.f);
        // X1 = L @ X0
        gemm(L, X0, nullptr, X1, Nn, cols, Nn, 1.f, 0.f);
        // Y += X1 @ w1
        gemm(X1, w + (size_t)Fin * Fout, Yb, Yb, rows, Fout, Fin, 1.f, 1.f);
        // X2 = 2 L @ X1 - X0
        gemm(L, X1, X0, X2, Nn, cols, Nn, 2.f, -1.f);
        // Y += X2 @ w2
        gemm(X2, w + 2 * (size_t)Fin * Fout, Yb, Yb, rows, Fout, Fin, 1.f, 1.f);
        // X3 = 2 L @ X2 - X1  (into X0)
        gemm(L, X2, X1, X0, Nn, cols, Nn, 2.f, -1.f);
        // Y += X3 @ w3
        gemm(X0, w + 3 * (size_t)Fin * Fout, Yb, Yb, rows, Fout, Fin, 1.f, 1.f);
    };

    auto stats = [&](int rows, int F, const float* gam, const float* bet) {
        k_bn_partial<<<CHUNKS, 256>>>(Yb, rows, F, Pt);
        k_bn_final<<<1, 256>>>(Pt, F, (float)rows, gam, bet, BNp);
    };
    auto elgrid = [](int total) { return (total + 255) / 256; };

    // ---- input transpose: (4,8,8,8,768) -> node-major (768,256,8) ----
    {
        int total = 768 * Bt * 8;
        k_transpose_in<<<elgrid(total), 256>>>(x, X0, total);
    }

    // ---- e3a: L3, 8 -> 32 ----
    cheb(L3, 768, 8, 32, w_e3a);
    stats(768 * Bt, 32, g_e3a, b_e3a);
    k_bn_apply<<<elgrid(768 * Bt * 32), 256>>>(Yb, BNp, X0, 768 * Bt * 32, 32);

    // ---- e3b: L3, 32 -> 64 ; s3 skip + pool ----
    cheb(L3, 768, 32, 64, w_e3b);
    stats(768 * Bt, 64, g_e3b, b_e3b);
    k_bn_apply<<<elgrid(768 * Bt * 64), 256>>>(Yb, BNp, S3, 768 * Bt * 64, 64);
    k_bn_pool<<<elgrid(192 * Bt * 64), 256>>>(Yb, BNp, X0, 192 * Bt * 64, 64, Bt * 64);

    // ---- e2: L2, 64 -> 128 ; s2 skip + pool ----
    cheb(L2, 192, 64, 128, w_e2);
    stats(192 * Bt, 128, g_e2, b_e2);
    k_bn_apply<<<elgrid(192 * Bt * 128), 256>>>(Yb, BNp, S2, 192 * Bt * 128, 128);
    k_bn_pool<<<elgrid(48 * Bt * 128), 256>>>(Yb, BNp, X0, 48 * Bt * 128, 128, Bt * 128);

    // ---- e1: L1, 128 -> 256 ; s1 skip + pool ----
    cheb(L1, 48, 128, 256, w_e1);
    stats(48 * Bt, 256, g_e1, b_e1);
    k_bn_apply<<<elgrid(48 * Bt * 256), 256>>>(Yb, BNp, S1, 48 * Bt * 256, 256);
    k_bn_pool<<<elgrid(12 * Bt * 256), 256>>>(Yb, BNp, X0, 12 * Bt * 256, 256, Bt * 256);

    // ---- e0: L0, 256 -> 256 ----
    cheb(L0, 12, 256, 256, w_e0);
    stats(12 * Bt, 256, g_e0, b_e0);
    // unpool(bn(h)) -> X0 cols [0,256), skip s1 -> cols [256,512), Ftot=512
    k_bn_unpool_cat<<<elgrid(48 * Bt * 256), 256>>>(Yb, BNp, X0, 48 * Bt * 256, 256, 512, Bt);
    k_copy_cat<<<elgrid(48 * Bt * 256), 256>>>(S1, X0, 48 * Bt * 256, 256, 512, 256);

    // ---- d1: L1, 512 -> 128 ----
    cheb(L1, 48, 512, 128, w_d1);
    stats(48 * Bt, 128, g_d1, b_d1);
    k_bn_unpool_cat<<<elgrid(192 * Bt * 128), 256>>>(Yb, BNp, X0, 192 * Bt * 128, 128, 256, Bt);
    k_copy_cat<<<elgrid(192 * Bt * 128), 256>>>(S2, X0, 192 * Bt * 128, 128, 256, 128);

    // ---- d2: L2, 256 -> 64 ----
    cheb(L2, 192, 256, 64, w_d2);
    stats(192 * Bt, 64, g_d2, b_d2);
    k_bn_unpool_cat<<<elgrid(768 * Bt * 64), 256>>>(Yb, BNp, X0, 768 * Bt * 64, 64, 128, Bt);
    k_copy_cat<<<elgrid(768 * Bt * 64), 256>>>(S3, X0, 768 * Bt * 64, 64, 128, 64);

    // ---- d3: L3, 128 -> 32 ----
    cheb(L3, 768, 128, 32, w_d3);
    stats(768 * Bt, 32, g_d3, b_d3);
    k_bn_apply<<<elgrid(768 * Bt * 32), 256>>>(Yb, BNp, X0, 768 * Bt * 32, 32);

    // ---- out: L3, 32 -> 1 (no BN) ----
    cheb(L3, 768, 32, 1, w_out);

    // ---- output transpose -> (4,1,8,8,768) ----
    k_transpose_out<<<elgrid(196608), 256>>>(Yb, out);
}

// round 7
// speedup vs baseline: 2.4471x; 2.4471x over previous
#include <cuda_runtime.h>
#include <math.h>

// ---------------- static workspace (no allocations allowed) ----------------
#define CHUNKS 256
__device__ float g_x0[25165824];   // Xall / decoder-input buffer (max 768*256*128)
__device__ float g_x1[25165824];   // P buffer (decoder taps), max 768*256*4*32
__device__ float g_x2[25165824];   // B2 at 0, B1 at +8388608
__device__ float g_y [12582912];   // conv output Y (max 768*256*64)
__device__ float g_s3[12582912];
__device__ float g_s2[ 6291456];
__device__ float g_s1[ 3145728];
__device__ float g_part[CHUNKS * 512];
__device__ float g_bnp[512];

#define COFF(c,sh,st,msk) ((((c)>>(sh))*(st)) + ((c)&(msk)))
#define CONTIG_SH 30

// ------------- templated SGEMM with strided-submatrix operands -------------
// C = alpha*A@B + beta*D + gamma*E
// A: contiguous row-major (lda). B/C/D/E addressed as ptr + row*ld + COFF(col).
template<int BM,int BN,int BK,int TM,int TN>
__global__ __launch_bounds__((BM/TM)*(BN/TN)) void gemm_t(
    const float* __restrict__ A, int lda,
    const float* __restrict__ B, int ldb, int shB, int stB,
    float* __restrict__ C, int ldc, int shC, int stC,
    const float* __restrict__ Dp, int ldd, int shD, int stD, float beta,
    const float* __restrict__ Ep, int lde, int shE, int stE, float gamma,
    int M, int N, int K, float alpha)
{
    constexpr int THREADS = (BM/TM)*(BN/TN);
    constexpr int A4 = (BM*BK)/(4*THREADS);
    constexpr int B4 = (BK*BN)/(4*THREADS);
    __shared__ float As[2][BK][BM+4];
    __shared__ float Bs[2][BK][BN];

    const int tid = threadIdx.x;
    const int tx = tid % (BN/TN);
    const int ty = tid / (BN/TN);
    const int m0 = blockIdx.y*BM, n0 = blockIdx.x*BN;
    const int mskB = (1<<shB)-1;

    float acc[TM][TN] = {};
    float pa[A4*4], pb[B4*4];

    const int nt = (K + BK - 1)/BK;

    auto load = [&](int k0){
#pragma unroll
        for (int s=0;s<A4;s++){
            int slot = tid + s*THREADS;
            int r = slot/(BK/4);
            int cc = (slot - r*(BK/4))*4;
            int gr = m0+r, gc = k0+cc;
            float4 v = make_float4(0.f,0.f,0.f,0.f);
            if (gr < M){
                const float* p = A + (size_t)gr*lda;
                if (gc+3 < K) v = *(const float4*)(p+gc);
                else {
                    if (gc   < K) v.x = p[gc];
                    if (gc+1 < K) v.y = p[gc+1];
                    if (gc+2 < K) v.z = p[gc+2];
                }
            }
            pa[s*4+0]=v.x; pa[s*4+1]=v.y; pa[s*4+2]=v.z; pa[s*4+3]=v.w;
        }
#pragma unroll
        for (int s=0;s<B4;s++){
            int slot = tid + s*THREADS;
            int r = slot/(BN/4);
            int cc = (slot - r*(BN/4))*4;
            int gr = k0+r, gc = n0+cc;
            float4 v = make_float4(0.f,0.f,0.f,0.f);
            if (gr < K){
                const float* p = B + (size_t)gr*ldb;
                if (mskB >= 3 && gc+3 < N){
                    v = *(const float4*)(p + COFF(gc,shB,stB,mskB));
                } else {
                    if (gc   < N) v.x = p[COFF(gc  ,shB,stB,mskB)];
                    if (gc+1 < N) v.y = p[COFF(gc+1,shB,stB,mskB)];
                    if (gc+2 < N) v.z = p[COFF(gc+2,shB,stB,mskB)];
                    if (gc+3 < N) v.w = p[COFF(gc+3,shB,stB,mskB)];
                }
            }
            pb[s*4+0]=v.x; pb[s*4+1]=v.y; pb[s*4+2]=v.z; pb[s*4+3]=v.w;
        }
    };
    auto stage = [&](int buf){
#pragma unroll
        for (int s=0;s<A4;s++){
            int slot = tid + s*THREADS;
            int r = slot/(BK/4);
            int cc = (slot - r*(BK/4))*4;
            As[buf][cc+0][r] = pa[s*4+0];
            As[buf][cc+1][r] = pa[s*4+1];
            As[buf][cc+2][r] = pa[s*4+2];
            As[buf][cc+3][r] = pa[s*4+3];
        }
#pragma unroll
        for (int s=0;s<B4;s++){
            int slot = tid + s*THREADS;
            int r = slot/(BN/4);
            int cc = (slot - r*(BN/4))*4;
            *(float4*)&Bs[buf][r][cc] = make_float4(pb[s*4+0],pb[s*4+1],pb[s*4+2],pb[s*4+3]);
        }
    };

    load(0); stage(0); __syncthreads();
    for (int t=0; t<nt; t++){
        int cur = t & 1;
        if (t+1 < nt) load((t+1)*BK);
#pragma unroll
        for (int kk=0; kk<BK; kk++){
            float a[TM], b[TN];
#pragma unroll
            for (int i=0;i<TM;i++) a[i] = As[cur][kk][ty*TM+i];
#pragma unroll
            for (int j=0;j<TN;j++) b[j] = Bs[cur][kk][tx*TN+j];
#pragma unroll
            for (int i=0;i<TM;i++)
#pragma unroll
                for (int j=0;j<TN;j++) acc[i][j] = fmaf(a[i], b[j], acc[i][j]);
        }
        if (t+1 < nt){ stage(cur^1); __syncthreads(); }
    }

    const int mskC=(1<<shC)-1, mskD=(1<<shD)-1, mskE=(1<<shE)-1;
#pragma unroll
    for (int i=0;i<TM;i++){
        int r = m0 + ty*TM + i;
        if (r >= M) break;
        size_t rC = (size_t)r*ldc;
        size_t rD = (size_t)r*ldd;
        size_t rE = (size_t)r*lde;
#pragma unroll
        for (int j=0;j<TN;j++){
            int c = n0 + tx*TN + j;
            if (c >= N) break;
            float v = alpha*acc[i][j];
            if (Dp) v += beta  * Dp[rD + COFF(c,shD,stD,mskD)];
            if (Ep) v += gamma * Ep[rE + COFF(c,shE,stE,mskE)];
            C[rC + COFF(c,shC,stC,mskC)] = v;
        }
    }
}

// ---------------- elementwise / reduction kernels ----------------

__global__ __launch_bounds__(256) void k_transpose_in(const float* __restrict__ x,
                                                      float* __restrict__ dst, int total, int ld)
{
    int i = blockIdx.x * blockDim.x + threadIdx.x;
    if (i >= total) return;
    int c  = i & 7;
    int bt = (i >> 3) & 255;
    int n  = i >> 11;
    int b  = bt >> 6, hw = bt & 63;
    int row = n * 256 + bt;
    dst[(size_t)row * ld + c] = x[(((b << 3) + c) * 64 + hw) * 768 + n];
}

__global__ __launch_bounds__(256) void k_bn_partial(const float* __restrict__ Y,
                                                    int rows, int F, float* __restrict__ part)
{
    __shared__ float sh[512];
    int blk = blockIdx.x;
    int rpc = (rows + CHUNKS - 1) / CHUNKS;
    int r0 = blk * rpc;
    int r1 = rows < r0 + rpc ? rows : r0 + rpc;
    int tid = threadIdx.x;
    int c = tid % F;
    int g = tid / F;
    int GP = blockDim.x / F;
    float s = 0.f, q = 0.f;
    for (int r = r0 + g; r < r1; r += GP) {
        float v = Y[(size_t)r * F + c];
        s += v; q += v * v;
    }
    sh[tid] = s;
    sh[256 + tid] = q;
    __syncthreads();
    if (g == 0) {
        for (int gg = 1; gg < GP; gg++) {
            s += sh[gg * F + c];
            q += sh[256 + gg * F + c];
        }
        part[blk * 2 * F + c] = s;
        part[blk * 2 * F + F + c] = q;
    }
}

__global__ __launch_bounds__(256) void k_bn_final(const float* __restrict__ part, int F, float cnt,
                                                  const float* __restrict__ gam,
                                                  const float* __restrict__ bet,
                                                  float* __restrict__ bn)
{
    int c = threadIdx.x;
    if (c >= F) return;
    float s = 0.f, q = 0.f;
    for (int ch = 0; ch < CHUNKS; ch++) {
        s += part[ch * 2 * F + c];
        q += part[ch * 2 * F + F + c];
    }
    float mean = s / cnt;
    float var = q / cnt - mean * mean;
    float sc = gam[c] * rsqrtf(var + 1e-5f);
    bn[c] = sc;
    bn[F + c] = bet[c] - mean * sc;
}

// bn+relu, dst row stride ld (dst cols [0,F) of ld-wide rows)
__global__ __launch_bounds__(256) void k_bn_apply(const float* __restrict__ Y,
                                                  const float* __restrict__ bn,
                                                  float* __restrict__ dst, int total, int F, int ld)
{
    int i = blockIdx.x * blockDim.x + threadIdx.x;
    if (i >= total) return;
    int c = i % F;
    int r = i / F;
    float v = Y[i] * bn[c] + bn[F + c];
    dst[(size_t)r * ld + c] = v > 0.f ? v : 0.f;
}

// bn + relu + 4:1 max-pool over node dim, strided dst
__global__ __launch_bounds__(256) void k_bn_pool(const float* __restrict__ Y,
                                                 const float* __restrict__ bn,
                                                 float* __restrict__ dst,
                                                 int total, int F, int BtF, int ldo)
{
    int i = blockIdx.x * blockDim.x + threadIdx.x;
    if (i >= total) return;
    int c = i % F;
    int inner = i % BtF;
    int j = i / BtF;
    float sc = bn[c], shf = bn[F + c];
    size_t base = (size_t)(4 * j) * BtF + inner;
    float m = Y[base] * sc + shf;
#pragma unroll
    for (int q = 1; q < 4; q++) {
        float v = Y[base + (size_t)q * BtF] * sc + shf;
        if (v > m) m = v;
    }
    int r = i / F;
    dst[(size_t)r * ldo + c] = m > 0.f ? m : 0.f;
}

__global__ __launch_bounds__(256) void k_bn_unpool_cat(const float* __restrict__ Y,
                                                       const float* __restrict__ bn,
                                                       float* __restrict__ dst,
                                                       int total, int F1, int Ftot, int Bt)
{
    int i = blockIdx.x * blockDim.x + threadIdx.x;
    if (i >= total) return;
    int f = i % F1;
    int r = i / F1;
    int bt = r % Bt;
    int n = r / Bt;
    int j = n >> 2;
    float v = Y[((size_t)j * Bt + bt) * F1 + f] * bn[f] + bn[F1 + f];
    dst[(size_t)r * Ftot + f] = v > 0.f ? v : 0.f;
}

__global__ __launch_bounds__(256) void k_copy_cat(const float* __restrict__ S,
                                                  float* __restrict__ dst,
                                                  int total, int Fs, int Ftot, int off)
{
    int i = blockIdx.x * blockDim.x + threadIdx.x;
    if (i >= total) return;
    int f = i % Fs;
    int r = i / Fs;
    dst[(size_t)r * Ftot + off + f] = S[i];
}

__global__ __launch_bounds__(256) void k_transpose_out(const float* __restrict__ Y,
                                                       float* __restrict__ out)
{
    int i = blockIdx.x * blockDim.x + threadIdx.x;
    if (i >= 196608) return;
    int n = i % 768, bt = i / 768;
    out[i] = Y[n * 256 + bt];
}

// ---------------- host orchestration ----------------
static inline int ilog2i(int x){ int s = 0; while ((1 << s) < x) s++; return s; }

static void gemm_go(const float* A,int lda,
                    const float* B,int ldb,int shB,int stB,
                    float* C,int ldc,int shC,int stC,
                    const float* D,int ldd,int shD,int stD,float beta,
                    const float* E,int lde,int shE,int stE,float gamma,
                    int M,int N,int K,float alpha)
{
    if (N >= 96){
        dim3 g((N+127)/128,(M+127)/128);
        gemm_t<128,128,16,8,8><<<g,256>>>(A,lda,B,ldb,shB,stB,C,ldc,shC,stC,
                                          D,ldd,shD,stD,beta,E,lde,shE,stE,gamma,M,N,K,alpha);
    } else if (N >= 48){
        dim3 g((N+63)/64,(M+127)/128);
        gemm_t<128,64,16,8,8><<<g,128>>>(A,lda,B,ldb,shB,stB,C,ldc,shC,stC,
                                         D,ldd,shD,stD,beta,E,lde,shE,stE,gamma,M,N,K,alpha);
    } else {
        dim3 g((N+31)/32,(M+127)/128);
        gemm_t<128,32,16,8,4><<<g,128>>>(A,lda,B,ldb,shB,stB,C,ldc,shC,stC,
                                         D,ldd,shD,stD,beta,E,lde,shE,stE,gamma,M,N,K,alpha);
    }
}

extern "C" void kernel_launch(void* const* d_in, const int* in_sizes, int n_in,
                              void* d_out, int out_size)
{
    const float* x    = (const float*)d_in[0];
    const float* L3   = (const float*)d_in[1];
    const float* L2   = (const float*)d_in[2];
    const float* L1   = (const float*)d_in[3];
    const float* L0   = (const float*)d_in[4];
    const float* w_e3a = (const float*)d_in[5];
    const float* g_e3a = (const float*)d_in[6];
    const float* b_e3a = (const float*)d_in[7];
    const float* w_e3b = (const float*)d_in[8];
    const float* g_e3b = (const float*)d_in[9];
    const float* b_e3b = (const float*)d_in[10];
    const float* w_e2  = (const float*)d_in[11];
    const float* g_e2  = (const float*)d_in[12];
    const float* b_e2  = (const float*)d_in[13];
    const float* w_e1  = (const float*)d_in[14];
    const float* g_e1  = (const float*)d_in[15];
    const float* b_e1  = (const float*)d_in[16];
    const float* w_e0  = (const float*)d_in[17];
    const float* g_e0  = (const float*)d_in[18];
    const float* b_e0  = (const float*)d_in[19];
    const float* w_d1  = (const float*)d_in[20];
    const float* g_d1  = (const float*)d_in[21];
    const float* b_d1  = (const float*)d_in[22];
    const float* w_d2  = (const float*)d_in[23];
    const float* g_d2  = (const float*)d_in[24];
    const float* b_d2  = (const float*)d_in[25];
    const float* w_d3  = (const float*)d_in[26];
    const float* g_d3  = (const float*)d_in[27];
    const float* b_d3  = (const float*)d_in[28];
    const float* w_out = (const float*)d_in[29];
    float* out = (float*)d_out;

    float *Xb, *Pb, *Bb, *Yb, *S3, *S2, *S1, *Pt, *BNp;
    cudaGetSymbolAddress((void**)&Xb, g_x0);
    cudaGetSymbolAddress((void**)&Pb, g_x1);
    cudaGetSymbolAddress((void**)&Bb, g_x2);
    cudaGetSymbolAddress((void**)&Yb, g_y);
    cudaGetSymbolAddress((void**)&S3, g_s3);
    cudaGetSymbolAddress((void**)&S2, g_s2);
    cudaGetSymbolAddress((void**)&S1, g_s1);
    cudaGetSymbolAddress((void**)&Pt, g_part);
    cudaGetSymbolAddress((void**)&BNp, g_bnp);
    float* B2 = Bb;
    float* B1 = Bb + 8388608;

    const int Bt = 256;
    const int CMSK_ST = 0;   // contiguous: sh=CONTIG_SH, st=0

    // Encoder cheb: forward recurrence in Xall (rows, 4*Fin), fused tap GEMM.
    auto enc = [&](const float* L, int Nn, int Fin, int Fout, const float* w){
        int rows = Nn * Bt;
        int ld4  = 4 * Fin;
        int ldr  = Bt * ld4;           // logical (Nn, Bt*Fin) row stride
        int sh   = ilog2i(Fin);
        int Nw   = Bt * Fin;
        // X1 = L @ X0
        gemm_go(L, Nn, Xb, ldr, sh, ld4, Xb + Fin, ldr, sh, ld4,
                nullptr,1,CONTIG_SH,CMSK_ST,0.f, nullptr,1,CONTIG_SH,CMSK_ST,0.f,
                Nn, Nw, Nn, 1.f);
        // X2 = 2 L X1 - X0
        gemm_go(L, Nn, Xb + Fin, ldr, sh, ld4, Xb + 2*Fin, ldr, sh, ld4,
                Xb, ldr, sh, ld4, -1.f, nullptr,1,CONTIG_SH,CMSK_ST,0.f,
                Nn, Nw, Nn, 2.f);
        // X3 = 2 L X2 - X1
        gemm_go(L, Nn, Xb + 2*Fin, ldr, sh, ld4, Xb + 3*Fin, ldr, sh, ld4,
                Xb + Fin, ldr, sh, ld4, -1.f, nullptr,1,CONTIG_SH,CMSK_ST,0.f,
                Nn, Nw, Nn, 2.f);
        // Y = [X0|X1|X2|X3] @ w   (w is (4*Fin, Fout) contiguous natively)
        gemm_go(Xb, ld4, w, Fout, CONTIG_SH, CMSK_ST, Yb, Fout, CONTIG_SH, CMSK_ST,
                nullptr,1,CONTIG_SH,CMSK_ST,0.f, nullptr,1,CONTIG_SH,CMSK_ST,0.f,
                rows, Fout, ld4, 1.f);
    };

    // Decoder cheb: taps first (N-stacked into P), then Clenshaw on width Bt*Fout.
    auto dec = [&](const float* L, int Nn, int Fin, int Fout, const float* w){
        int rows = Nn * Bt;
        int ld4  = 4 * Fout;
        int ldr  = Bt * ld4;           // logical (Nn, Bt*Fout) row stride for P views
        int sh   = ilog2i(Fout);
        int Nw   = Bt * Fout;
        // P = X @ W'  where W'(f, k*Fout+o) = w[k][f][o] via strided B addressing
        gemm_go(Xb, Fin, w, Fout, sh, Fin*Fout, Pb, ld4, CONTIG_SH, CMSK_ST,
                nullptr,1,CONTIG_SH,CMSK_ST,0.f, nullptr,1,CONTIG_SH,CMSK_ST,0.f,
                rows, ld4, Fin, 1.f);
        // b2 = 2 L P3 + P2
        gemm_go(L, Nn, Pb + 3*Fout, ldr, sh, ld4, B2, Nw, CONTIG_SH, CMSK_ST,
                Pb + 2*Fout, ldr, sh, ld4, 1.f, nullptr,1,CONTIG_SH,CMSK_ST,0.f,
                Nn, Nw, Nn, 2.f);
        // b1 = 2 L b2 + P1 - P3
        gemm_go(L, Nn, B2, Nw, CONTIG_SH, CMSK_ST, B1, Nw, CONTIG_SH, CMSK_ST,
                Pb + Fout, ldr, sh, ld4, 1.f, Pb + 3*Fout, ldr, sh, ld4, -1.f,
                Nn, Nw, Nn, 2.f);
        // y = L b1 + P0 - b2
        gemm_go(L, Nn, B1, Nw, CONTIG_SH, CMSK_ST, Yb, Nw, CONTIG_SH, CMSK_ST,
                Pb, ldr, sh, ld4, 1.f, B2, Nw, CONTIG_SH, CMSK_ST, -1.f,
                Nn, Nw, Nn, 1.f);
    };

    auto stats = [&](int rows, int F, const float* gam, const float* bet){
        k_bn_partial<<<CHUNKS, 256>>>(Yb, rows, F, Pt);
        k_bn_final<<<1, 256>>>(Pt, F, (float)rows, gam, bet, BNp);
    };
    auto elgrid = [](int total){ return (total + 255) / 256; };

    // ---- input transpose into e3a Xall X0 region (ld=32) ----
    k_transpose_in<<<elgrid(768*Bt*8), 256>>>(x, Xb, 768*Bt*8, 32);

    // ---- e3a: L3, 8 -> 32 ----
    enc(L3, 768, 8, 32, w_e3a);
    stats(196608, 32, g_e3a, b_e3a);
    k_bn_apply<<<elgrid(196608*32), 256>>>(Yb, BNp, Xb, 196608*32, 32, 128);

    // ---- e3b: L3, 32 -> 64 ; skip s3 + pool into e2 X0 region ----
    enc(L3, 768, 32, 64, w_e3b);
    stats(196608, 64, g_e3b, b_e3b);
    k_bn_apply<<<elgrid(196608*64), 256>>>(Yb, BNp, S3, 196608*64, 64, 64);
    k_bn_pool<<<elgrid(192*Bt*64), 256>>>(Yb, BNp, Xb, 192*Bt*64, 64, Bt*64, 256);

    // ---- e2: L2, 64 -> 128 ----
    enc(L2, 192, 64, 128, w_e2);
    stats(49152, 128, g_e2, b_e2);
    k_bn_apply<<<elgrid(49152*128), 256>>>(Yb, BNp, S2, 49152*128, 128, 128);
    k_bn_pool<<<elgrid(48*Bt*128), 256>>>(Yb, BNp, Xb, 48*Bt*128, 128, Bt*128, 512);

    // ---- e1: L1, 128 -> 256 ----
    enc(L1, 48, 128, 256, w_e1);
    stats(12288, 256, g_e1, b_e1);
    k_bn_apply<<<elgrid(12288*256), 256>>>(Yb, BNp, S1, 12288*256, 256, 256);
    k_bn_pool<<<elgrid(12*Bt*256), 256>>>(Yb, BNp, Xb, 12*Bt*256, 256, Bt*256, 1024);

    // ---- e0: L0, 256 -> 256 ----
    enc(L0, 12, 256, 256, w_e0);
    stats(3072, 256, g_e0, b_e0);
    // decoder input d1: unpool(bn(h)) cols [0,256) + S1 cols [256,512)
    k_bn_unpool_cat<<<elgrid(12288*256), 256>>>(Yb, BNp, Xb, 12288*256, 256, 512, Bt);
    k_copy_cat<<<elgrid(12288*256), 256>>>(S1, Xb, 12288*256, 256, 512, 256);

    // ---- d1: L1, 512 -> 128 ----
    dec(L1, 48, 512, 128, w_d1);
    stats(12288, 128, g_d1, b_d1);
    k_bn_unpool_cat<<<elgrid(49152*128), 256>>>(Yb, BNp, Xb, 49152*128, 128, 256, Bt);
    k_copy_cat<<<elgrid(49152*128), 256>>>(S2, Xb, 49152*128, 128, 256, 128);

    // ---- d2: L2, 256 -> 64 ----
    dec(L2, 192, 256, 64, w_d2);
    stats(49152, 64, g_d2, b_d2);
    k_bn_unpool_cat<<<elgrid(196608*64), 256>>>(Yb, BNp, Xb, 196608*64, 64, 128, Bt);
    k_copy_cat<<<elgrid(196608*64), 256>>>(S3, Xb, 196608*64, 64, 128, 64);

    // ---- d3: L3, 128 -> 32 ----
    dec(L3, 768, 128, 32, w_d3);
    stats(196608, 32, g_d3, b_d3);
    k_bn_apply<<<elgrid(196608*32), 256>>>(Yb, BNp, Xb, 196608*32, 32, 32);

    // ---- out: L3, 32 -> 1 (no BN) ----
    dec(L3, 768, 32, 1, w_out);

    // ---- output transpose -> (4,1,8,8,768) ----
    k_transpose_out<<<elgrid(196608), 256>>>(Yb, out);
}

// round 11
// speedup vs baseline: 5.2476x; 2.1445x over previous
#include <cuda_runtime.h>
#include <math.h>

// ---------------- static workspace (no allocations allowed) ----------------
#define CHUNKS 256
#define MAXNZ 96
__device__ float g_x0[25165824];   // Xall / decoder-input buffer
__device__ float g_x1[25165824];   // P buffer (decoder taps)
__device__ float g_x2[25165824];   // B2 at 0, B1 at +8388608
__device__ float g_y [12582912];   // conv output Y
__device__ float g_s3[12582912];
__device__ float g_s2[ 6291456];
__device__ float g_s1[ 3145728];
__device__ float g_part[CHUNKS * 512];
__device__ float g_bnp[512];
// sparse Laplacian structure: 4 levels
__device__ int   g_scols[4 * 768 * MAXNZ];
__device__ float g_svals[4 * 768 * MAXNZ];
__device__ int   g_scnt [4 * 768];

#define COFF(c,sh,st,msk) ((((c)>>(sh))*(st)) + ((c)&(msk)))
#define CONTIG_SH 30

// ---------------- sparse structure build (exact-zero test) ----------------
__global__ __launch_bounds__(256) void k_build_sparse(const float* __restrict__ L, int Nn,
                                                      int* __restrict__ cols,
                                                      float* __restrict__ vals,
                                                      int* __restrict__ cnt)
{
    int r = blockIdx.x * blockDim.x + threadIdx.x;
    if (r >= Nn) return;
    int k = 0;
    for (int c = 0; c < Nn; c++) {
        float v = L[(size_t)r * Nn + c];
        if (v != 0.0f) {
            if (k < MAXNZ) { cols[r * MAXNZ + k] = c; vals[r * MAXNZ + k] = v; }
            k++;
        }
    }
    cnt[r] = k < MAXNZ ? k : MAXNZ;
}

// ---------------- SpMM: Y = alpha * L@X + beta*D + gamma*E ----------------
// operand addressing: ptr + (size_t)node*ldn + COFF(c, sh, st, msk), c in [0,W)
__global__ __launch_bounds__(256) void spmm_k(
    const int* __restrict__ cols, const float* __restrict__ vals, const int* __restrict__ cnt,
    const float* __restrict__ X, int ldx, int shx, int stx,
    float* __restrict__ Y, int ldy, int shy, int sty,
    const float* __restrict__ Dp, int ldd, int shd, int std_, float beta,
    const float* __restrict__ Ep, int lde, int she, int ste, float gamma,
    int W, float alpha)
{
    __shared__ float sv[MAXNZ];
    __shared__ int   sc[MAXNZ];
    int n = blockIdx.y;
    int tid = threadIdx.x;
    if (tid < MAXNZ) { sv[tid] = vals[n * MAXNZ + tid]; sc[tid] = cols[n * MAXNZ + tid]; }
    __syncthreads();
    int nz = cnt[n];
    int c = blockIdx.x * 1024 + tid * 4;
    if (c >= W) return;

    const int mskx = (1 << shx) - 1, msky = (1 << shy) - 1;
    const int mskd = (1 << shd) - 1, mske = (1 << she) - 1;
    bool vec = (mskx >= 3) && (msky >= 3) && (c + 3 < W)
            && (!Dp || mskd >= 3) && (!Ep || mske >= 3);

    if (vec) {
        size_t co = COFF(c, shx, stx, mskx);
        float4 acc = make_float4(0.f, 0.f, 0.f, 0.f);
        for (int j = 0; j < nz; j++) {
            float v = sv[j];
            const float4 xv = *(const float4*)(X + (size_t)sc[j] * ldx + co);
            acc.x = fmaf(v, xv.x, acc.x);
            acc.y = fmaf(v, xv.y, acc.y);
            acc.z = fmaf(v, xv.z, acc.z);
            acc.w = fmaf(v, xv.w, acc.w);
        }
        acc.x *= alpha; acc.y *= alpha; acc.z *= alpha; acc.w *= alpha;
        if (Dp) {
            const float4 dv = *(const float4*)(Dp + (size_t)n * ldd + COFF(c, shd, std_, mskd));
            acc.x = fmaf(beta, dv.x, acc.x);
            acc.y = fmaf(beta, dv.y, acc.y);
            acc.z = fmaf(beta, dv.z, acc.z);
            acc.w = fmaf(beta, dv.w, acc.w);
        }
        if (Ep) {
            const float4 ev = *(const float4*)(Ep + (size_t)n * lde + COFF(c, she, ste, mske));
            acc.x = fmaf(gamma, ev.x, acc.x);
            acc.y = fmaf(gamma, ev.y, acc.y);
            acc.z = fmaf(gamma, ev.z, acc.z);
            acc.w = fmaf(gamma, ev.w, acc.w);
        }
        *(float4*)(Y + (size_t)n * ldy + COFF(c, shy, sty, msky)) = acc;
    } else {
#pragma unroll
        for (int q = 0; q < 4; q++) {
            int cc = c + q;
            if (cc >= W) break;
            float acc = 0.f;
            size_t co = COFF(cc, shx, stx, mskx);
            for (int j = 0; j < nz; j++)
                acc = fmaf(sv[j], X[(size_t)sc[j] * ldx + co], acc);
            acc *= alpha;
            if (Dp) acc = fmaf(beta,  Dp[(size_t)n * ldd + COFF(cc, shd, std_, mskd)], acc);
            if (Ep) acc = fmaf(gamma, Ep[(size_t)n * lde + COFF(cc, she, ste, mske)], acc);
            Y[(size_t)n * ldy + COFF(cc, shy, sty, msky)] = acc;
        }
    }
}

// ------------- templated SGEMM with strided-submatrix operands -------------
template<int BM,int BN,int BK,int TM,int TN>
__global__ __launch_bounds__((BM/TM)*(BN/TN), 2) void gemm_t(
    const float* __restrict__ A, int lda,
    const float* __restrict__ B, int ldb, int shB, int stB,
    float* __restrict__ C, int ldc, int shC, int stC,
    const float* __restrict__ Dp, int ldd, int shD, int stD, float beta,
    const float* __restrict__ Ep, int lde, int shE, int stE, float gamma,
    int M, int N, int K, float alpha)
{
    constexpr int THREADS = (BM/TM)*(BN/TN);
    constexpr int A4 = (BM*BK)/(4*THREADS);
    constexpr int B4 = (BK*BN)/(4*THREADS);
    __shared__ float As[2][BK][BM+4];
    __shared__ float Bs[2][BK][BN];

    const int tid = threadIdx.x;
    const int tx = tid % (BN/TN);
    const int ty = tid / (BN/TN);
    const int m0 = blockIdx.y*BM, n0 = blockIdx.x*BN;
    const int mskB = (1<<shB)-1;

    float acc[TM][TN] = {};
    float pa[A4*4], pb[B4*4];

    const int nt = (K + BK - 1)/BK;

    auto load = [&](int k0){
#pragma unroll
        for (int s=0;s<A4;s++){
            int slot = tid + s*THREADS;
            int r = slot/(BK/4);
            int cc = (slot - r*(BK/4))*4;
            int gr = m0+r, gc = k0+cc;
            float4 v = make_float4(0.f,0.f,0.f,0.f);
            if (gr < M){
                const float* p = A + (size_t)gr*lda;
                if (gc+3 < K) v = *(const float4*)(p+gc);
                else {
                    if (gc   < K) v.x = p[gc];
                    if (gc+1 < K) v.y = p[gc+1];
                    if (gc+2 < K) v.z = p[gc+2];
                }
            }
            pa[s*4+0]=v.x; pa[s*4+1]=v.y; pa[s*4+2]=v.z; pa[s*4+3]=v.w;
        }
#pragma unroll
        for (int s=0;s<B4;s++){
            int slot = tid + s*THREADS;
            int r = slot/(BN/4);
            int cc = (slot - r*(BN/4))*4;
            int gr = k0+r, gc = n0+cc;
            float4 v = make_float4(0.f,0.f,0.f,0.f);
            if (gr < K){
                const float* p = B + (size_t)gr*ldb;
                if (mskB >= 3 && gc+3 < N){
                    v = *(const float4*)(p + COFF(gc,shB,stB,mskB));
                } else {
                    if (gc   < N) v.x = p[COFF(gc  ,shB,stB,mskB)];
                    if (gc+1 < N) v.y = p[COFF(gc+1,shB,stB,mskB)];
                    if (gc+2 < N) v.z = p[COFF(gc+2,shB,stB,mskB)];
                    if (gc+3 < N) v.w = p[COFF(gc+3,shB,stB,mskB)];
                }
            }
            pb[s*4+0]=v.x; pb[s*4+1]=v.y; pb[s*4+2]=v.z; pb[s*4+3]=v.w;
        }
    };
    auto stage = [&](int buf){
#pragma unroll
        for (int s=0;s<A4;s++){
            int slot = tid + s*THREADS;
            int r = slot/(BK/4);
            int cc = (slot - r*(BK/4))*4;
            As[buf][cc+0][r] = pa[s*4+0];
            As[buf][cc+1][r] = pa[s*4+1];
            As[buf][cc+2][r] = pa[s*4+2];
            As[buf][cc+3][r] = pa[s*4+3];
        }
#pragma unroll
        for (int s=0;s<B4;s++){
            int slot = tid + s*THREADS;
            int r = slot/(BN/4);
            int cc = (slot - r*(BN/4))*4;
            *(float4*)&Bs[buf][r][cc] = make_float4(pb[s*4+0],pb[s*4+1],pb[s*4+2],pb[s*4+3]);
        }
    };

    load(0); stage(0); __syncthreads();
    for (int t=0; t<nt; t++){
        int cur = t & 1;
        if (t+1 < nt) load((t+1)*BK);
#pragma unroll
        for (int kk=0; kk<BK; kk++){
            float a[TM], b[TN];
#pragma unroll
            for (int i=0;i<TM;i++) a[i] = As[cur][kk][ty*TM+i];
#pragma unroll
            for (int j=0;j<TN;j++) b[j] = Bs[cur][kk][tx*TN+j];
#pragma unroll
            for (int i=0;i<TM;i++)
#pragma unroll
                for (int j=0;j<TN;j++) acc[i][j] = fmaf(a[i], b[j], acc[i][j]);
        }
        if (t+1 < nt){ stage(cur^1); __syncthreads(); }
    }

    const int mskC=(1<<shC)-1, mskD=(1<<shD)-1, mskE=(1<<shE)-1;
#pragma unroll
    for (int i=0;i<TM;i++){
        int r = m0 + ty*TM + i;
        if (r >= M) break;
        size_t rC = (size_t)r*ldc;
        size_t rD = (size_t)r*ldd;
        size_t rE = (size_t)r*lde;
#pragma unroll
        for (int j=0;j<TN;j++){
            int c = n0 + tx*TN + j;
            if (c >= N) break;
            float v = alpha*acc[i][j];
            if (Dp) v += beta  * Dp[rD + COFF(c,shD,stD,mskD)];
            if (Ep) v += gamma * Ep[rE + COFF(c,shE,stE,mskE)];
            C[rC + COFF(c,shC,stC,mskC)] = v;
        }
    }
}

// ---------------- elementwise / reduction kernels ----------------

__global__ __launch_bounds__(256) void k_transpose_in(const float* __restrict__ x,
                                                      float* __restrict__ dst, int total, int ld)
{
    int i = blockIdx.x * blockDim.x + threadIdx.x;
    if (i >= total) return;
    int c  = i & 7;
    int bt = (i >> 3) & 255;
    int n  = i >> 11;
    int b  = bt >> 6, hw = bt & 63;
    int row = n * 256 + bt;
    dst[(size_t)row * ld + c] = x[(((b << 3) + c) * 64 + hw) * 768 + n];
}

__global__ __launch_bounds__(256) void k_bn_partial(const float* __restrict__ Y,
                                                    int rows, int F, float* __restrict__ part)
{
    __shared__ float sh[512];
    int blk = blockIdx.x;
    int rpc = (rows + CHUNKS - 1) / CHUNKS;
    int r0 = blk * rpc;
    int r1 = rows < r0 + rpc ? rows : r0 + rpc;
    int tid = threadIdx.x;
    int c = tid % F;
    int g = tid / F;
    int GP = blockDim.x / F;
    float s = 0.f, q = 0.f;
    for (int r = r0 + g; r < r1; r += GP) {
        float v = Y[(size_t)r * F + c];
        s += v; q += v * v;
    }
    sh[tid] = s;
    sh[256 + tid] = q;
    __syncthreads();
    if (g == 0) {
        for (int gg = 1; gg < GP; gg++) {
            s += sh[gg * F + c];
            q += sh[256 + gg * F + c];
        }
        part[blk * 2 * F + c] = s;
        part[blk * 2 * F + F + c] = q;
    }
}

__global__ __launch_bounds__(256) void k_bn_final(const float* __restrict__ part, int F, float cnt,
                                                  const float* __restrict__ gam,
                                                  const float* __restrict__ bet,
                                                  float* __restrict__ bn)
{
    int c = threadIdx.x;
    if (c >= F) return;
    float s = 0.f, q = 0.f;
    for (int ch = 0; ch < CHUNKS; ch++) {
        s += part[ch * 2 * F + c];
        q += part[ch * 2 * F + F + c];
    }
    float mean = s / cnt;
    float var = q / cnt - mean * mean;
    float sc = gam[c] * rsqrtf(var + 1e-5f);
    bn[c] = sc;
    bn[F + c] = bet[c] - mean * sc;
}

__global__ __launch_bounds__(256) void k_bn_apply(const float* __restrict__ Y,
                                                  const float* __restrict__ bn,
                                                  float* __restrict__ dst, int total, int F, int ld)
{
    int i = blockIdx.x * blockDim.x + threadIdx.x;
    if (i >= total) return;
    int c = i % F;
    int r = i / F;
    float v = Y[i] * bn[c] + bn[F + c];
    dst[(size_t)r * ld + c] = v > 0.f ? v : 0.f;
}

__global__ __launch_bounds__(256) void k_bn_pool(const float* __restrict__ Y,
                                                 const float* __restrict__ bn,
                                                 float* __restrict__ dst,
                                                 int total, int F, int BtF, int ldo)
{
    int i = blockIdx.x * blockDim.x + threadIdx.x;
    if (i >= total) return;
    int c = i % F;
    int inner = i % BtF;
    int j = i / BtF;
    float sc = bn[c], shf = bn[F + c];
    size_t base = (size_t)(4 * j) * BtF + inner;
    float m = Y[base] * sc + shf;
#pragma unroll
    for (int q = 1; q < 4; q++) {
        float v = Y[base + (size_t)q * BtF] * sc + shf;
        if (v > m) m = v;
    }
    int r = i / F;
    dst[(size_t)r * ldo + c] = m > 0.f ? m : 0.f;
}

__global__ __launch_bounds__(256) void k_bn_unpool_cat(const float* __restrict__ Y,
                                                       const float* __restrict__ bn,
                                                       float* __restrict__ dst,
                                                       int total, int F1, int Ftot, int Bt)
{
    int i = blockIdx.x * blockDim.x + threadIdx.x;
    if (i >= total) return;
    int f = i % F1;
    int r = i / F1;
    int bt = r % Bt;
    int n = r / Bt;
    int j = n >> 2;
    float v = Y[((size_t)j * Bt + bt) * F1 + f] * bn[f] + bn[F1 + f];
    dst[(size_t)r * Ftot + f] = v > 0.f ? v : 0.f;
}

__global__ __launch_bounds__(256) void k_copy_cat(const float* __restrict__ S,
                                                  float* __restrict__ dst,
                                                  int total, int Fs, int Ftot, int off)
{
    int i = blockIdx.x * blockDim.x + threadIdx.x;
    if (i >= total) return;
    int f = i % Fs;
    int r = i / Fs;
    dst[(size_t)r * Ftot + off + f] = S[i];
}

__global__ __launch_bounds__(256) void k_transpose_out(const float* __restrict__ Y,
                                                       float* __restrict__ out)
{
    int i = blockIdx.x * blockDim.x + threadIdx.x;
    if (i >= 196608) return;
    int n = i % 768, bt = i / 768;
    out[i] = Y[n * 256 + bt];
}

// ---------------- host orchestration ----------------
static inline int ilog2i(int x){ int s = 0; while ((1 << s) < x) s++; return s; }

static void gemm_go(const float* A,int lda,
                    const float* B,int ldb,int shB,int stB,
                    float* C,int ldc,int shC,int stC,
                    const float* D,int ldd,int shD,int stD,float beta,
                    const float* E,int lde,int shE,int stE,float gamma,
                    int M,int N,int K,float alpha)
{
    if (N >= 96){
        dim3 g((N+127)/128,(M+127)/128);
        gemm_t<128,128,16,8,8><<<g,256>>>(A,lda,B,ldb,shB,stB,C,ldc,shC,stC,
                                          D,ldd,shD,stD,beta,E,lde,shE,stE,gamma,M,N,K,alpha);
    } else if (N >= 48){
        dim3 g((N+63)/64,(M+127)/128);
        gemm_t<128,64,16,8,8><<<g,128>>>(A,lda,B,ldb,shB,stB,C,ldc,shC,stC,
                                         D,ldd,shD,stD,beta,E,lde,shE,stE,gamma,M,N,K,alpha);
    } else {
        dim3 g((N+31)/32,(M+127)/128);
        gemm_t<128,32,16,8,4><<<g,128>>>(A,lda,B,ldb,shB,stB,C,ldc,shC,stC,
                                         D,ldd,shD,stD,beta,E,lde,shE,stE,gamma,M,N,K,alpha);
    }
}

extern "C" void kernel_launch(void* const* d_in, const int* in_sizes, int n_in,
                              void* d_out, int out_size)
{
    const float* x    = (const float*)d_in[0];
    const float* L3   = (const float*)d_in[1];
    const float* L2   = (const float*)d_in[2];
    const float* L1   = (const float*)d_in[3];
    const float* L0   = (const float*)d_in[4];
    const float* w_e3a = (const float*)d_in[5];
    const float* g_e3a = (const float*)d_in[6];
    const float* b_e3a = (const float*)d_in[7];
    const float* w_e3b = (const float*)d_in[8];
    const float* g_e3b = (const float*)d_in[9];
    const float* b_e3b = (const float*)d_in[10];
    const float* w_e2  = (const float*)d_in[11];
    const float* g_e2  = (const float*)d_in[12];
    const float* b_e2  = (const float*)d_in[13];
    const float* w_e1  = (const float*)d_in[14];
    const float* g_e1  = (const float*)d_in[15];
    const float* b_e1  = (const float*)d_in[16];
    const float* w_e0  = (const float*)d_in[17];
    const float* g_e0  = (const float*)d_in[18];
    const float* b_e0  = (const float*)d_in[19];
    const float* w_d1  = (const float*)d_in[20];
    const float* g_d1  = (const float*)d_in[21];
    const float* b_d1  = (const float*)d_in[22];
    const float* w_d2  = (const float*)d_in[23];
    const float* g_d2  = (const float*)d_in[24];
    const float* b_d2  = (const float*)d_in[25];
    const float* w_d3  = (const float*)d_in[26];
    const float* g_d3  = (const float*)d_in[27];
    const float* b_d3  = (const float*)d_in[28];
    const float* w_out = (const float*)d_in[29];
    float* out = (float*)d_out;

    float *Xb, *Pb, *Bb, *Yb, *S3, *S2, *S1, *Pt, *BNp, *SV;
    int *SC, *SN;
    cudaGetSymbolAddress((void**)&Xb, g_x0);
    cudaGetSymbolAddress((void**)&Pb, g_x1);
    cudaGetSymbolAddress((void**)&Bb, g_x2);
    cudaGetSymbolAddress((void**)&Yb, g_y);
    cudaGetSymbolAddress((void**)&S3, g_s3);
    cudaGetSymbolAddress((void**)&S2, g_s2);
    cudaGetSymbolAddress((void**)&S1, g_s1);
    cudaGetSymbolAddress((void**)&Pt, g_part);
    cudaGetSymbolAddress((void**)&BNp, g_bnp);
    cudaGetSymbolAddress((void**)&SC, g_scols);
    cudaGetSymbolAddress((void**)&SV, g_svals);
    cudaGetSymbolAddress((void**)&SN, g_scnt);
    float* B2 = Bb;
    float* B1 = Bb + 8388608;

    const int Bt = 256;
    const int CS = CONTIG_SH;

    // ---- build sparse Laplacian structure (runs each replay, deterministic) ----
    k_build_sparse<<<3, 256>>>(L3, 768, SC + 0*768*MAXNZ, SV + 0*768*MAXNZ, SN + 0*768);
    k_build_sparse<<<1, 256>>>(L2, 192, SC + 1*768*MAXNZ, SV + 1*768*MAXNZ, SN + 1*768);
    k_build_sparse<<<1, 256>>>(L1,  48, SC + 2*768*MAXNZ, SV + 2*768*MAXNZ, SN + 2*768);
    k_build_sparse<<<1, 256>>>(L0,  12, SC + 3*768*MAXNZ, SV + 3*768*MAXNZ, SN + 3*768);

    auto spmm = [&](int lev, int Nn,
                    const float* X,int ldx,int shx,int stx,
                    float* Y,int ldy,int shy,int sty,
                    const float* D,int ldd,int shd,int std_,float beta,
                    const float* E,int lde,int she,int ste,float gamma,
                    int W, float alpha){
        dim3 g((W + 1023)/1024, Nn);
        spmm_k<<<g, 256>>>(SC + lev*768*MAXNZ, SV + lev*768*MAXNZ, SN + lev*768,
                           X,ldx,shx,stx, Y,ldy,shy,sty,
                           D,ldd,shd,std_,beta, E,lde,she,ste,gamma, W, alpha);
    };

    // Encoder cheb: forward recurrence via SpMM in Xall, fused tap GEMM.
    auto enc = [&](int lev, int Nn, int Fin, int Fout, const float* w){
        int rows = Nn * Bt;
        int ld4  = 4 * Fin;
        int ldn  = Bt * ld4;
        int sh   = ilog2i(Fin);
        int Nw   = Bt * Fin;
        // X1 = L X0
        spmm(lev, Nn, Xb, ldn, sh, ld4, Xb + Fin, ldn, sh, ld4,
             nullptr,1,CS,0,0.f, nullptr,1,CS,0,0.f, Nw, 1.f);
        // X2 = 2 L X1 - X0
        spmm(lev, Nn, Xb + Fin, ldn, sh, ld4, Xb + 2*Fin, ldn, sh, ld4,
             Xb, ldn, sh, ld4, -1.f, nullptr,1,CS,0,0.f, Nw, 2.f);
        // X3 = 2 L X2 - X1
        spmm(lev, Nn, Xb + 2*Fin, ldn, sh, ld4, Xb + 3*Fin, ldn, sh, ld4,
             Xb + Fin, ldn, sh, ld4, -1.f, nullptr,1,CS,0,0.f, Nw, 2.f);
        // Y = [X0|X1|X2|X3] @ w
        gemm_go(Xb, ld4, w, Fout, CS, 0, Yb, Fout, CS, 0,
                nullptr,1,CS,0,0.f, nullptr,1,CS,0,0.f, rows, Fout, ld4, 1.f);
    };

    // Decoder cheb: dense tap GEMM, then Clenshaw via SpMM on width Bt*Fout.
    auto dec = [&](int lev, int Nn, int Fin, int Fout, const float* w){
        int rows = Nn * Bt;
        int ld4  = 4 * Fout;
        int ldn  = Bt * ld4;
        int sh   = ilog2i(Fout);
        int Nw   = Bt * Fout;
        // P = X @ W'
        gemm_go(Xb, Fin, w, Fout, sh, Fin*Fout, Pb, ld4, CS, 0,
                nullptr,1,CS,0,0.f, nullptr,1,CS,0,0.f, rows, ld4, Fin, 1.f);
        // b2 = 2 L P3 + P2
        spmm(lev, Nn, Pb + 3*Fout, ldn, sh, ld4, B2, Nw, CS, 0,
             Pb + 2*Fout, ldn, sh, ld4, 1.f, nullptr,1,CS,0,0.f, Nw, 2.f);
        // b1 = 2 L b2 + P1 - P3
        spmm(lev, Nn, B2, Nw, CS, 0, B1, Nw, CS, 0,
             Pb + Fout, ldn, sh, ld4, 1.f, Pb + 3*Fout, ldn, sh, ld4, -1.f, Nw, 2.f);
        // y = L b1 + P0 - b2
        spmm(lev, Nn, B1, Nw, CS, 0, Yb, Nw, CS, 0,
             Pb, ldn, sh, ld4, 1.f, B2, Nw, CS, 0, -1.f, Nw, 1.f);
    };

    auto stats = [&](int rows, int F, const float* gam, const float* bet){
        k_bn_partial<<<CHUNKS, 256>>>(Yb, rows, F, Pt);
        k_bn_final<<<1, 256>>>(Pt, F, (float)rows, gam, bet, BNp);
    };
    auto elgrid = [](int total){ return (total + 255) / 256; };

    // ---- input transpose into e3a Xall X0 region (ld=32) ----
    k_transpose_in<<<elgrid(768*Bt*8), 256>>>(x, Xb, 768*Bt*8, 32);

    // ---- e3a: L3, 8 -> 32 ----
    enc(0, 768, 8, 32, w_e3a);
    stats(196608, 32, g_e3a, b_e3a);
    k_bn_apply<<<elgrid(196608*32), 256>>>(Yb, BNp, Xb, 196608*32, 32, 128);

    // ---- e3b: L3, 32 -> 64 ; skip s3 + pool into e2 X0 region ----
    enc(0, 768, 32, 64, w_e3b);
    stats(196608, 64, g_e3b, b_e3b);
    k_bn_apply<<<elgrid(196608*64), 256>>>(Yb, BNp, S3, 196608*64, 64, 64);
    k_bn_pool<<<elgrid(192*Bt*64), 256>>>(Yb, BNp, Xb, 192*Bt*64, 64, Bt*64, 256);

    // ---- e2: L2, 64 -> 128 ----
    enc(1, 192, 64, 128, w_e2);
    stats(49152, 128, g_e2, b_e2);
    k_bn_apply<<<elgrid(49152*128), 256>>>(Yb, BNp, S2, 49152*128, 128, 128);
    k_bn_pool<<<elgrid(48*Bt*128), 256>>>(Yb, BNp, Xb, 48*Bt*128, 128, Bt*128, 512);

    // ---- e1: L1, 128 -> 256 ----
    enc(2, 48, 128, 256, w_e1);
    stats(12288, 256, g_e1, b_e1);
    k_bn_apply<<<elgrid(12288*256), 256>>>(Yb, BNp, S1, 12288*256, 256, 256);
    k_bn_pool<<<elgrid(12*Bt*256), 256>>>(Yb, BNp, Xb, 12*Bt*256, 256, Bt*256, 1024);

    // ---- e0: L0, 256 -> 256 ----
    enc(3, 12, 256, 256, w_e0);
    stats(3072, 256, g_e0, b_e0);
    k_bn_unpool_cat<<<elgrid(12288*256), 256>>>(Yb, BNp, Xb, 12288*256, 256, 512, Bt);
    k_copy_cat<<<elgrid(12288*256), 256>>>(S1, Xb, 12288*256, 256, 512, 256);

    // ---- d1: L1, 512 -> 128 ----
    dec(2, 48, 512, 128, w_d1);
    stats(12288, 128, g_d1, b_d1);
    k_bn_unpool_cat<<<elgrid(49152*128), 256>>>(Yb, BNp, Xb, 49152*128, 128, 256, Bt);
    k_copy_cat<<<elgrid(49152*128), 256>>>(S2, Xb, 49152*128, 128, 256, 128);

    // ---- d2: L2, 256 -> 64 ----
    dec(1, 192, 256, 64, w_d2);
    stats(49152, 64, g_d2, b_d2);
    k_bn_unpool_cat<<<elgrid(196608*64), 256>>>(Yb, BNp, Xb, 196608*64, 64, 128, Bt);
    k_copy_cat<<<elgrid(196608*64), 256>>>(S3, Xb, 196608*64, 64, 128, 64);

    // ---- d3: L3, 128 -> 32 ----
    dec(0, 768, 128, 32, w_d3);
    stats(196608, 32, g_d3, b_d3);
    k_bn_apply<<<elgrid(196608*32), 256>>>(Yb, BNp, Xb, 196608*32, 32, 32);

    // ---- out: L3, 32 -> 1 (no BN) ----
    dec(0, 768, 32, 1, w_out);

    // ---- output transpose -> (4,1,8,8,768) ----
    k_transpose_out<<<elgrid(196608), 256>>>(Yb, out);
}

// round 16
// speedup vs baseline: 7.8942x; 1.5043x over previous
#include <cuda_runtime.h>
#include <cuda_bf16.h>
#include <stdint.h>
#include <math.h>

// ---------------- static workspace (no allocations allowed) ----------------
#define CHUNKS 256
#define MAXNZ 96
__device__ float g_x0[25165824];
__device__ float g_x1[25165824];
__device__ float g_x2[25165824];
__device__ float g_y [12582912];
__device__ float g_s3[12582912];
__device__ float g_s2[ 6291456];
__device__ float g_s1[ 3145728];
__device__ float g_part[CHUNKS * 512];
__device__ float g_bnp[512];
__device__ int   g_scols[4 * 768 * MAXNZ];
__device__ float g_svals[4 * 768 * MAXNZ];
__device__ int   g_scnt [4 * 768];
__device__ __align__(16) __nv_bfloat16 g_bth[262144];   // packed weight hi, [N][K]
__device__ __align__(16) __nv_bfloat16 g_btl[262144];   // packed weight lo, [N][K]

#define COFF(c,sh,st,msk) ((((c)>>(sh))*(st)) + ((c)&(msk)))
#define CONTIG_SH 30

// ---------------- weight pack: W' -> bf16 hi/lo, [N][K] K-major ----------------
__global__ __launch_bounds__(256) void k_pack_w(const float* __restrict__ w,
                                                __nv_bfloat16* __restrict__ bh,
                                                __nv_bfloat16* __restrict__ bl,
                                                int K, int Fd, int sB, int sA, int total)
{
    int i = blockIdx.x * blockDim.x + threadIdx.x;
    if (i >= total) return;
    int n = i / K, kk = i % K;
    float v = w[kk * sA + (n / Fd) * sB + (n % Fd)];
    __nv_bfloat16 h = __float2bfloat16_rn(v);
    bh[i] = h;
    bl[i] = __float2bfloat16_rn(v - __bfloat162float(h));
}

// ---------------- HMMA GEMM: C = A(fp32) @ B^T via bf16x3 mma.sync ----------------
__device__ __forceinline__ void mma16816(float c[4], const uint32_t a[4], const uint32_t b[2])
{
    asm volatile(
        "mma.sync.aligned.m16n8k16.row.col.f32.bf16.bf16.f32 "
        "{%0,%1,%2,%3}, {%4,%5,%6,%7}, {%8,%9}, {%0,%1,%2,%3};"
        : "+f"(c[0]), "+f"(c[1]), "+f"(c[2]), "+f"(c[3])
        : "r"(a[0]), "r"(a[1]), "r"(a[2]), "r"(a[3]), "r"(b[0]), "r"(b[1]));
}
__device__ __forceinline__ uint32_t pack_bf2(__nv_bfloat16 lo, __nv_bfloat16 hi)
{
    return ((uint32_t)__bfloat16_as_ushort(hi) << 16) | __bfloat16_as_ushort(lo);
}

// A: [M][K] fp32 (M%128==0, K%32==0). Bh/Bl: [N][K] bf16 (N%BN==0). C: [M][N] fp32.
template<int BN>
__global__ __launch_bounds__(256) void mgemm_k(
    const float* __restrict__ A,
    const __nv_bfloat16* __restrict__ Bh, const __nv_bfloat16* __restrict__ Bl,
    float* __restrict__ C, int M, int N, int K)
{
    constexpr int BM = 128, BK = 32;
    constexpr int WGN = BN / 32;      // warps along n (warp n-tile = 32)
    constexpr int WGM = 8 / WGN;      // warps along m
    constexpr int WTM = BM / WGM;     // warp m-tile
    constexpr int FM = WTM / 16;      // m16 fragments per warp
    constexpr int LDSR = BK + 8;      // 40 bf16 per row (conflict-free frag loads)

    __shared__ __nv_bfloat16 Ah[BM * LDSR], Al[BM * LDSR];
    __shared__ __nv_bfloat16 Bhs[BN * LDSR], Bls[BN * LDSR];

    const int tid = threadIdx.x, lane = tid & 31, wid = tid >> 5;
    const int m0 = blockIdx.x * BM, n0 = blockIdx.y * BN;
    const int wm = wid / WGN, wn = wid % WGN;
    const int g = lane >> 2, tig = lane & 3;

    float acc[FM][4][4] = {};

    for (int k0 = 0; k0 < K; k0 += BK) {
        // ---- stage A (128x32 fp32 -> bf16 hi/lo) ----
#pragma unroll
        for (int s = tid; s < 1024; s += 256) {
            int r = s >> 3, cg = (s & 7) << 2;
            const float4 v = *(const float4*)(A + (size_t)(m0 + r) * K + k0 + cg);
            __nv_bfloat16 h0 = __float2bfloat16_rn(v.x);
            __nv_bfloat16 h1 = __float2bfloat16_rn(v.y);
            __nv_bfloat16 h2 = __float2bfloat16_rn(v.z);
            __nv_bfloat16 h3 = __float2bfloat16_rn(v.w);
            __nv_bfloat16 l0 = __float2bfloat16_rn(v.x - __bfloat162float(h0));
            __nv_bfloat16 l1 = __float2bfloat16_rn(v.y - __bfloat162float(h1));
            __nv_bfloat16 l2 = __float2bfloat16_rn(v.z - __bfloat162float(h2));
            __nv_bfloat16 l3 = __float2bfloat16_rn(v.w - __bfloat162float(h3));
            *(uint2*)&Ah[r * LDSR + cg] = make_uint2(pack_bf2(h0, h1), pack_bf2(h2, h3));
            *(uint2*)&Al[r * LDSR + cg] = make_uint2(pack_bf2(l0, l1), pack_bf2(l2, l3));
        }
        // ---- stage B (BNx32 bf16 hi/lo) ----
#pragma unroll
        for (int s = tid; s < BN * 4; s += 256) {
            int r = s >> 2, cg = (s & 3) << 3;
            size_t src = (size_t)(n0 + r) * K + k0 + cg;
            const uint4 vh = *(const uint4*)(Bh + src);
            const uint4 vl = *(const uint4*)(Bl + src);
            *(uint2*)&Bhs[r * LDSR + cg]     = make_uint2(vh.x, vh.y);
            *(uint2*)&Bhs[r * LDSR + cg + 4] = make_uint2(vh.z, vh.w);
            *(uint2*)&Bls[r * LDSR + cg]     = make_uint2(vl.x, vl.y);
            *(uint2*)&Bls[r * LDSR + cg + 4] = make_uint2(vl.z, vl.w);
        }
        __syncthreads();

#pragma unroll
        for (int ks = 0; ks < 2; ks++) {
            const int cb = ks * 16 + 2 * tig;
            uint32_t ah[FM][4], al[FM][4], bh[4][2], bl[4][2];
#pragma unroll
            for (int f = 0; f < FM; f++) {
                int r0 = wm * WTM + f * 16 + g;
                ah[f][0] = *(const uint32_t*)&Ah[r0 * LDSR + cb];
                ah[f][1] = *(const uint32_t*)&Ah[(r0 + 8) * LDSR + cb];
                ah[f][2] = *(const uint32_t*)&Ah[r0 * LDSR + cb + 8];
                ah[f][3] = *(const uint32_t*)&Ah[(r0 + 8) * LDSR + cb + 8];
                al[f][0] = *(const uint32_t*)&Al[r0 * LDSR + cb];
                al[f][1] = *(const uint32_t*)&Al[(r0 + 8) * LDSR + cb];
                al[f][2] = *(const uint32_t*)&Al[r0 * LDSR + cb + 8];
                al[f][3] = *(const uint32_t*)&Al[(r0 + 8) * LDSR + cb + 8];
            }
#pragma unroll
            for (int j = 0; j < 4; j++) {
                int rn = wn * 32 + j * 8 + g;
                bh[j][0] = *(const uint32_t*)&Bhs[rn * LDSR + cb];
                bh[j][1] = *(const uint32_t*)&Bhs[rn * LDSR + cb + 8];
                bl[j][0] = *(const uint32_t*)&Bls[rn * LDSR + cb];
                bl[j][1] = *(const uint32_t*)&Bls[rn * LDSR + cb + 8];
            }
#pragma unroll
            for (int f = 0; f < FM; f++)
#pragma unroll
                for (int j = 0; j < 4; j++) {
                    mma16816(acc[f][j], ah[f], bh[j]);
                    mma16816(acc[f][j], ah[f], bl[j]);
                    mma16816(acc[f][j], al[f], bh[j]);
                }
        }
        __syncthreads();
    }

    // ---- epilogue ----
#pragma unroll
    for (int f = 0; f < FM; f++) {
        int r0 = m0 + wm * WTM + f * 16 + g;
#pragma unroll
        for (int j = 0; j < 4; j++) {
            int cc = n0 + wn * 32 + j * 8 + 2 * tig;
            *(float2*)(C + (size_t)r0 * N + cc)       = make_float2(acc[f][j][0], acc[f][j][1]);
            *(float2*)(C + (size_t)(r0 + 8) * N + cc) = make_float2(acc[f][j][2], acc[f][j][3]);
        }
    }
}

// ---------------- sparse structure build (exact-zero test) ----------------
__global__ __launch_bounds__(256) void k_build_sparse(const float* __restrict__ L, int Nn,
                                                      int* __restrict__ cols,
                                                      float* __restrict__ vals,
                                                      int* __restrict__ cnt)
{
    int r = blockIdx.x * blockDim.x + threadIdx.x;
    if (r >= Nn) return;
    int k = 0;
    for (int c = 0; c < Nn; c++) {
        float v = L[(size_t)r * Nn + c];
        if (v != 0.0f) {
            if (k < MAXNZ) { cols[r * MAXNZ + k] = c; vals[r * MAXNZ + k] = v; }
            k++;
        }
    }
    cnt[r] = k < MAXNZ ? k : MAXNZ;
}

// ---------------- SpMM: Y = alpha * L@X + beta*D + gamma*E ----------------
__global__ __launch_bounds__(256) void spmm_k(
    const int* __restrict__ cols, const float* __restrict__ vals, const int* __restrict__ cnt,
    const float* __restrict__ X, int ldx, int shx, int stx,
    float* __restrict__ Y, int ldy, int shy, int sty,
    const float* __restrict__ Dp, int ldd, int shd, int std_, float beta,
    const float* __restrict__ Ep, int lde, int she, int ste, float gamma,
    int W, float alpha)
{
    __shared__ float sv[MAXNZ];
    __shared__ int   sc[MAXNZ];
    int n = blockIdx.y;
    int tid = threadIdx.x;
    if (tid < MAXNZ) { sv[tid] = vals[n * MAXNZ + tid]; sc[tid] = cols[n * MAXNZ + tid]; }
    __syncthreads();
    int nz = cnt[n];
    int c = blockIdx.x * 1024 + tid * 4;
    if (c >= W) return;

    const int mskx = (1 << shx) - 1, msky = (1 << shy) - 1;
    const int mskd = (1 << shd) - 1, mske = (1 << she) - 1;
    bool vec = (mskx >= 3) && (msky >= 3) && (c + 3 < W)
            && (!Dp || mskd >= 3) && (!Ep || mske >= 3);

    if (vec) {
        size_t co = COFF(c, shx, stx, mskx);
        float4 acc = make_float4(0.f, 0.f, 0.f, 0.f);
        for (int j = 0; j < nz; j++) {
            float v = sv[j];
            const float4 xv = *(const float4*)(X + (size_t)sc[j] * ldx + co);
            acc.x = fmaf(v, xv.x, acc.x);
            acc.y = fmaf(v, xv.y, acc.y);
            acc.z = fmaf(v, xv.z, acc.z);
            acc.w = fmaf(v, xv.w, acc.w);
        }
        acc.x *= alpha; acc.y *= alpha; acc.z *= alpha; acc.w *= alpha;
        if (Dp) {
            const float4 dv = *(const float4*)(Dp + (size_t)n * ldd + COFF(c, shd, std_, mskd));
            acc.x = fmaf(beta, dv.x, acc.x);
            acc.y = fmaf(beta, dv.y, acc.y);
            acc.z = fmaf(beta, dv.z, acc.z);
            acc.w = fmaf(beta, dv.w, acc.w);
        }
        if (Ep) {
            const float4 ev = *(const float4*)(Ep + (size_t)n * lde + COFF(c, she, ste, mske));
            acc.x = fmaf(gamma, ev.x, acc.x);
            acc.y = fmaf(gamma, ev.y, acc.y);
            acc.z = fmaf(gamma, ev.z, acc.z);
            acc.w = fmaf(gamma, ev.w, acc.w);
        }
        *(float4*)(Y + (size_t)n * ldy + COFF(c, shy, sty, msky)) = acc;
    } else {
#pragma unroll
        for (int q = 0; q < 4; q++) {
            int cc = c + q;
            if (cc >= W) break;
            float acc = 0.f;
            size_t co = COFF(cc, shx, stx, mskx);
            for (int j = 0; j < nz; j++)
                acc = fmaf(sv[j], X[(size_t)sc[j] * ldx + co], acc);
            acc *= alpha;
            if (Dp) acc = fmaf(beta,  Dp[(size_t)n * ldd + COFF(cc, shd, std_, mskd)], acc);
            if (Ep) acc = fmaf(gamma, Ep[(size_t)n * lde + COFF(cc, she, ste, mske)], acc);
            Y[(size_t)n * ldy + COFF(cc, shy, sty, msky)] = acc;
        }
    }
}

// ------------- FFMA SGEMM (small shapes: e3a tap, out tap) -------------
template<int BM,int BN,int BK,int TM,int TN>
__global__ __launch_bounds__((BM/TM)*(BN/TN), 2) void gemm_t(
    const float* __restrict__ A, int lda,
    const float* __restrict__ B, int ldb, int shB, int stB,
    float* __restrict__ C, int ldc, int shC, int stC,
    const float* __restrict__ Dp, int ldd, int shD, int stD, float beta,
    const float* __restrict__ Ep, int lde, int shE, int stE, float gamma,
    int M, int N, int K, float alpha)
{
    constexpr int THREADS = (BM/TM)*(BN/TN);
    constexpr int A4 = (BM*BK)/(4*THREADS);
    constexpr int B4 = (BK*BN)/(4*THREADS);
    __shared__ float As[2][BK][BM + 4];
    __shared__ float Bs[2][BK][BN];

    const int tid = threadIdx.x;
    const int tx = tid % (BN/TN);
    const int ty = tid / (BN/TN);
    const int m0 = blockIdx.y*BM, n0 = blockIdx.x*BN;
    const int mskB = (1<<shB)-1;

    float acc[TM][TN] = {};
    float pa[A4*4], pb[B4*4];
    const int nt = (K + BK - 1)/BK;

    auto load = [&](int k0){
#pragma unroll
        for (int s=0;s<A4;s++){
            int slot = tid + s*THREADS;
            int r = slot/(BK/4);
            int cc = (slot - r*(BK/4))*4;
            int gr = m0+r, gc = k0+cc;
            float4 v = make_float4(0.f,0.f,0.f,0.f);
            if (gr < M){
                const float* p = A + (size_t)gr*lda;
                if (gc+3 < K) v = *(const float4*)(p+gc);
                else {
                    if (gc   < K) v.x = p[gc];
                    if (gc+1 < K) v.y = p[gc+1];
                    if (gc+2 < K) v.z = p[gc+2];
                }
            }
            pa[s*4+0]=v.x; pa[s*4+1]=v.y; pa[s*4+2]=v.z; pa[s*4+3]=v.w;
        }
#pragma unroll
        for (int s=0;s<B4;s++){
            int slot = tid + s*THREADS;
            int r = slot/(BN/4);
            int cc = (slot - r*(BN/4))*4;
            int gr = k0+r, gc = n0+cc;
            float4 v = make_float4(0.f,0.f,0.f,0.f);
            if (gr < K){
                const float* p = B + (size_t)gr*ldb;
                if (mskB >= 3 && gc+3 < N){
                    v = *(const float4*)(p + COFF(gc,shB,stB,mskB));
                } else {
                    if (gc   < N) v.x = p[COFF(gc  ,shB,stB,mskB)];
                    if (gc+1 < N) v.y = p[COFF(gc+1,shB,stB,mskB)];
                    if (gc+2 < N) v.z = p[COFF(gc+2,shB,stB,mskB)];
                    if (gc+3 < N) v.w = p[COFF(gc+3,shB,stB,mskB)];
                }
            }
            pb[s*4+0]=v.x; pb[s*4+1]=v.y; pb[s*4+2]=v.z; pb[s*4+3]=v.w;
        }
    };
    auto stage = [&](int buf){
#pragma unroll
        for (int s=0;s<A4;s++){
            int slot = tid + s*THREADS;
            int r = slot/(BK/4);
            int cc = (slot - r*(BK/4))*4;
            As[buf][cc+0][r] = pa[s*4+0];
            As[buf][cc+1][r] = pa[s*4+1];
            As[buf][cc+2][r] = pa[s*4+2];
            As[buf][cc+3][r] = pa[s*4+3];
        }
#pragma unroll
        for (int s=0;s<B4;s++){
            int slot = tid + s*THREADS;
            int r = slot/(BN/4);
            int cc = (slot - r*(BN/4))*4;
            *(float4*)&Bs[buf][r][cc] = make_float4(pb[s*4+0],pb[s*4+1],pb[s*4+2],pb[s*4+3]);
        }
    };

    load(0); stage(0); __syncthreads();
    for (int t=0; t<nt; t++){
        int cur = t & 1;
        if (t+1 < nt) load((t+1)*BK);
#pragma unroll
        for (int kk=0; kk<BK; kk++){
            float a[TM], b[TN];
#pragma unroll
            for (int i=0;i<TM;i++) a[i] = As[cur][kk][ty*TM+i];
#pragma unroll
            for (int j=0;j<TN;j++) b[j] = Bs[cur][kk][tx*TN+j];
#pragma unroll
            for (int i=0;i<TM;i++)
#pragma unroll
                for (int j=0;j<TN;j++) acc[i][j] = fmaf(a[i], b[j], acc[i][j]);
        }
        if (t+1 < nt){ stage(cur^1); __syncthreads(); }
    }

    const int mskC=(1<<shC)-1, mskD=(1<<shD)-1, mskE=(1<<shE)-1;
#pragma unroll
    for (int i=0;i<TM;i++){
        int r = m0 + ty*TM + i;
        if (r >= M) break;
        size_t rC = (size_t)r*ldc;
        size_t rD = (size_t)r*ldd;
        size_t rE = (size_t)r*lde;
#pragma unroll
        for (int j=0;j<TN;j++){
            int c = n0 + tx*TN + j;
            if (c >= N) break;
            float v = alpha*acc[i][j];
            if (Dp) v += beta  * Dp[rD + COFF(c,shD,stD,mskD)];
            if (Ep) v += gamma * Ep[rE + COFF(c,shE,stE,mskE)];
            C[rC + COFF(c,shC,stC,mskC)] = v;
        }
    }
}

// ---------------- elementwise / reduction kernels ----------------

__global__ __launch_bounds__(256) void k_transpose_in(const float* __restrict__ x,
                                                      float* __restrict__ dst, int total, int ld)
{
    int i = blockIdx.x * blockDim.x + threadIdx.x;
    if (i >= total) return;
    int c  = i & 7;
    int bt = (i >> 3) & 255;
    int n  = i >> 11;
    int b  = bt >> 6, hw = bt & 63;
    int row = n * 256 + bt;
    dst[(size_t)row * ld + c] = x[(((b << 3) + c) * 64 + hw) * 768 + n];
}

__global__ __launch_bounds__(256) void k_bn_partial(const float* __restrict__ Y,
                                                    int rows, int F, float* __restrict__ part)
{
    __shared__ float sh[512];
    int blk = blockIdx.x;
    int rpc = (rows + CHUNKS - 1) / CHUNKS;
    int r0 = blk * rpc;
    int r1 = rows < r0 + rpc ? rows : r0 + rpc;
    int tid = threadIdx.x;
    int c = tid % F;
    int g = tid / F;
    int GP = blockDim.x / F;
    float s = 0.f, q = 0.f;
    for (int r = r0 + g; r < r1; r += GP) {
        float v = Y[(size_t)r * F + c];
        s += v; q += v * v;
    }
    sh[tid] = s;
    sh[256 + tid] = q;
    __syncthreads();
    if (g == 0) {
        for (int gg = 1; gg < GP; gg++) {
            s += sh[gg * F + c];
            q += sh[256 + gg * F + c];
        }
        part[blk * 2 * F + c] = s;
        part[blk * 2 * F + F + c] = q;
    }
}

__global__ __launch_bounds__(256) void k_bn_final(const float* __restrict__ part, int F, float cnt,
                                                  const float* __restrict__ gam,
                                                  const float* __restrict__ bet,
                                                  float* __restrict__ bn)
{
    int c = threadIdx.x;
    if (c >= F) return;
    float s = 0.f, q = 0.f;
    for (int ch = 0; ch < CHUNKS; ch++) {
        s += part[ch * 2 * F + c];
        q += part[ch * 2 * F + F + c];
    }
    float mean = s / cnt;
    float var = q / cnt - mean * mean;
    float sc = gam[c] * rsqrtf(var + 1e-5f);
    bn[c] = sc;
    bn[F + c] = bet[c] - mean * sc;
}

__global__ __launch_bounds__(256) void k_bn_apply(const float* __restrict__ Y,
                                                  const float* __restrict__ bn,
                                                  float* __restrict__ dst, int total, int F, int ld)
{
    int i = blockIdx.x * blockDim.x + threadIdx.x;
    if (i >= total) return;
    int c = i % F;
    int r = i / F;
    float v = Y[i] * bn[c] + bn[F + c];
    dst[(size_t)r * ld + c] = v > 0.f ? v : 0.f;
}

__global__ __launch_bounds__(256) void k_bn_pool(const float* __restrict__ Y,
                                                 const float* __restrict__ bn,
                                                 float* __restrict__ dst,
                                                 int total, int F, int BtF, int ldo)
{
    int i = blockIdx.x * blockDim.x + threadIdx.x;
    if (i >= total) return;
    int c = i % F;
    int inner = i % BtF;
    int j = i / BtF;
    float sc = bn[c], shf = bn[F + c];
    size_t base = (size_t)(4 * j) * BtF + inner;
    float m = Y[base] * sc + shf;
#pragma unroll
    for (int q = 1; q < 4; q++) {
        float v = Y[base + (size_t)q * BtF] * sc + shf;
        if (v > m) m = v;
    }
    int r = i / F;
    dst[(size_t)r * ldo + c] = m > 0.f ? m : 0.f;
}

__global__ __launch_bounds__(256) void k_bn_unpool_cat(const float* __restrict__ Y,
                                                       const float* __restrict__ bn,
                                                       float* __restrict__ dst,
                                                       int total, int F1, int Ftot, int Bt)
{
    int i = blockIdx.x * blockDim.x + threadIdx.x;
    if (i >= total) return;
    int f = i % F1;
    int r = i / F1;
    int bt = r % Bt;
    int n = r / Bt;
    int j = n >> 2;
    float v = Y[((size_t)j * Bt + bt) * F1 + f] * bn[f] + bn[F1 + f];
    dst[(size_t)r * Ftot + f] = v > 0.f ? v : 0.f;
}

__global__ __launch_bounds__(256) void k_copy_cat(const float* __restrict__ S,
                                                  float* __restrict__ dst,
                                                  int total, int Fs, int Ftot, int off)
{
    int i = blockIdx.x * blockDim.x + threadIdx.x;
    if (i >= total) return;
    int f = i % Fs;
    int r = i / Fs;
    dst[(size_t)r * Ftot + off + f] = S[i];
}

__global__ __launch_bounds__(256) void k_transpose_out(const float* __restrict__ Y,
                                                       float* __restrict__ out)
{
    int i = blockIdx.x * blockDim.x + threadIdx.x;
    if (i >= 196608) return;
    int n = i % 768, bt = i / 768;
    out[i] = Y[n * 256 + bt];
}

// ---------------- host orchestration ----------------
static inline int ilog2i(int x){ int s = 0; while ((1 << s) < x) s++; return s; }

static void gemm_go(const float* A,int lda,
                    const float* B,int ldb,int shB,int stB,
                    float* C,int ldc,int shC,int stC,
                    const float* D,int ldd,int shD,int stD,float beta,
                    const float* E,int lde,int shE,int stE,float gamma,
                    int M,int N,int K,float alpha)
{
    if (N >= 96){
        dim3 g((N+127)/128,(M+127)/128);
        gemm_t<128,128,16,8,8><<<g,256>>>(A,lda,B,ldb,shB,stB,C,ldc,shC,stC,
                                          D,ldd,shD,stD,beta,E,lde,shE,stE,gamma,M,N,K,alpha);
    } else if (N >= 48){
        dim3 g((N+63)/64,(M+127)/128);
        gemm_t<128,64,16,8,8><<<g,128>>>(A,lda,B,ldb,shB,stB,C,ldc,shC,stC,
                                         D,ldd,shD,stD,beta,E,lde,shE,stE,gamma,M,N,K,alpha);
    } else {
        dim3 g((N+31)/32,(M+127)/128);
        gemm_t<128,32,16,8,4><<<g,128>>>(A,lda,B,ldb,shB,stB,C,ldc,shC,stC,
                                         D,ldd,shD,stD,beta,E,lde,shE,stE,gamma,M,N,K,alpha);
    }
}

static void mgemm_go(const float* A, const __nv_bfloat16* Bh, const __nv_bfloat16* Bl,
                     float* C, int M, int N, int K)
{
    if (N % 128 == 0) {
        dim3 g(M / 128, N / 128);
        mgemm_k<128><<<g, 256>>>(A, Bh, Bl, C, M, N, K);
    } else {
        dim3 g(M / 128, N / 64);
        mgemm_k<64><<<g, 256>>>(A, Bh, Bl, C, M, N, K);
    }
}

extern "C" void kernel_launch(void* const* d_in, const int* in_sizes, int n_in,
                              void* d_out, int out_size)
{
    const float* x    = (const float*)d_in[0];
    const float* L3   = (const float*)d_in[1];
    const float* L2   = (const float*)d_in[2];
    const float* L1   = (const float*)d_in[3];
    const float* L0   = (const float*)d_in[4];
    const float* w_e3a = (const float*)d_in[5];
    const float* g_e3a = (const float*)d_in[6];
    const float* b_e3a = (const float*)d_in[7];
    const float* w_e3b = (const float*)d_in[8];
    const float* g_e3b = (const float*)d_in[9];
    const float* b_e3b = (const float*)d_in[10];
    const float* w_e2  = (const float*)d_in[11];
    const float* g_e2  = (const float*)d_in[12];
    const float* b_e2  = (const float*)d_in[13];
    const float* w_e1  = (const float*)d_in[14];
    const float* g_e1  = (const float*)d_in[15];
    const float* b_e1  = (const float*)d_in[16];
    const float* w_e0  = (const float*)d_in[17];
    const float* g_e0  = (const float*)d_in[18];
    const float* b_e0  = (const float*)d_in[19];
    const float* w_d1  = (const float*)d_in[20];
    const float* g_d1  = (const float*)d_in[21];
    const float* b_d1  = (const float*)d_in[22];
    const float* w_d2  = (const float*)d_in[23];
    const float* g_d2  = (const float*)d_in[24];
    const float* b_d2  = (const float*)d_in[25];
    const float* w_d3  = (const float*)d_in[26];
    const float* g_d3  = (const float*)d_in[27];
    const float* b_d3  = (const float*)d_in[28];
    const float* w_out = (const float*)d_in[29];
    float* out = (float*)d_out;

    float *Xb, *Pb, *Bb, *Yb, *S3, *S2, *S1, *Pt, *BNp, *SV;
    int *SC, *SN;
    __nv_bfloat16 *BtH, *BtL;
    cudaGetSymbolAddress((void**)&Xb, g_x0);
    cudaGetSymbolAddress((void**)&Pb, g_x1);
    cudaGetSymbolAddress((void**)&Bb, g_x2);
    cudaGetSymbolAddress((void**)&Yb, g_y);
    cudaGetSymbolAddress((void**)&S3, g_s3);
    cudaGetSymbolAddress((void**)&S2, g_s2);
    cudaGetSymbolAddress((void**)&S1, g_s1);
    cudaGetSymbolAddress((void**)&Pt, g_part);
    cudaGetSymbolAddress((void**)&BNp, g_bnp);
    cudaGetSymbolAddress((void**)&SC, g_scols);
    cudaGetSymbolAddress((void**)&SV, g_svals);
    cudaGetSymbolAddress((void**)&SN, g_scnt);
    cudaGetSymbolAddress((void**)&BtH, g_bth);
    cudaGetSymbolAddress((void**)&BtL, g_btl);
    float* B2 = Bb;
    float* B1 = Bb + 8388608;

    const int Bt = 256;
    const int CS = CONTIG_SH;

    // ---- build sparse Laplacian structure ----
    k_build_sparse<<<3, 256>>>(L3, 768, SC + 0*768*MAXNZ, SV + 0*768*MAXNZ, SN + 0*768);
    k_build_sparse<<<1, 256>>>(L2, 192, SC + 1*768*MAXNZ, SV + 1*768*MAXNZ, SN + 1*768);
    k_build_sparse<<<1, 256>>>(L1,  48, SC + 2*768*MAXNZ, SV + 2*768*MAXNZ, SN + 2*768);
    k_build_sparse<<<1, 256>>>(L0,  12, SC + 3*768*MAXNZ, SV + 3*768*MAXNZ, SN + 3*768);

    auto spmm = [&](int lev, int Nn,
                    const float* X,int ldx,int shx,int stx,
                    float* Y,int ldy,int shy,int sty,
                    const float* D,int ldd,int shd,int std_,float beta,
                    const float* E,int lde,int she,int ste,float gamma,
                    int W, float alpha){
        dim3 g((W + 1023)/1024, Nn);
        spmm_k<<<g, 256>>>(SC + lev*768*MAXNZ, SV + lev*768*MAXNZ, SN + lev*768,
                           X,ldx,shx,stx, Y,ldy,shy,sty,
                           D,ldd,shd,std_,beta, E,lde,she,ste,gamma, W, alpha);
    };

    // Encoder cheb: forward recurrence via SpMM in Xall, HMMA/FFMA tap GEMM.
    auto enc = [&](int lev, int Nn, int Fin, int Fout, const float* w){
        int rows = Nn * Bt;
        int ld4  = 4 * Fin;
        int ldn  = Bt * ld4;
        int sh   = ilog2i(Fin);
        int Nw   = Bt * Fin;
        spmm(lev, Nn, Xb, ldn, sh, ld4, Xb + Fin, ldn, sh, ld4,
             nullptr,1,CS,0,0.f, nullptr,1,CS,0,0.f, Nw, 1.f);
        spmm(lev, Nn, Xb + Fin, ldn, sh, ld4, Xb + 2*Fin, ldn, sh, ld4,
             Xb, ldn, sh, ld4, -1.f, nullptr,1,CS,0,0.f, Nw, 2.f);
        spmm(lev, Nn, Xb + 2*Fin, ldn, sh, ld4, Xb + 3*Fin, ldn, sh, ld4,
             Xb + Fin, ldn, sh, ld4, -1.f, nullptr,1,CS,0,0.f, Nw, 2.f);
        if (Fin >= 16 && (Fout % 64) == 0) {
            // Bt[n][kk] = w[kk*Fout + n]
            int tot = Fout * ld4;
            k_pack_w<<<(tot + 255)/256, 256>>>(w, BtH, BtL, ld4, Fout, 0, Fout, tot);
            mgemm_go(Xb, BtH, BtL, Yb, rows, Fout, ld4);
        } else {
            gemm_go(Xb, ld4, w, Fout, CS, 0, Yb, Fout, CS, 0,
                    nullptr,1,CS,0,0.f, nullptr,1,CS,0,0.f, rows, Fout, ld4, 1.f);
        }
    };

    // Decoder cheb: tap GEMM (HMMA/FFMA), then Clenshaw via SpMM.
    auto dec = [&](int lev, int Nn, int Fin, int Fout, const float* w){
        int rows = Nn * Bt;
        int ld4  = 4 * Fout;
        int ldn  = Bt * ld4;
        int sh   = ilog2i(Fout);
        int Nw   = Bt * Fout;
        if (Fout >= 32) {
            // Bt[n][f] = w[(n/Fout)*Fin*Fout + f*Fout + (n%Fout)]
            int tot = ld4 * Fin;
            k_pack_w<<<(tot + 255)/256, 256>>>(w, BtH, BtL, Fin, Fout, Fin*Fout, Fout, tot);
            mgemm_go(Xb, BtH, BtL, Pb, rows, ld4, Fin);
        } else {
            gemm_go(Xb, Fin, w, Fout, sh, Fin*Fout, Pb, ld4, CS, 0,
                    nullptr,1,CS,0,0.f, nullptr,1,CS,0,0.f, rows, ld4, Fin, 1.f);
        }
        spmm(lev, Nn, Pb + 3*Fout, ldn, sh, ld4, B2, Nw, CS, 0,
             Pb + 2*Fout, ldn, sh, ld4, 1.f, nullptr,1,CS,0,0.f, Nw, 2.f);
        spmm(lev, Nn, B2, Nw, CS, 0, B1, Nw, CS, 0,
             Pb + Fout, ldn, sh, ld4, 1.f, Pb + 3*Fout, ldn, sh, ld4, -1.f, Nw, 2.f);
        spmm(lev, Nn, B1, Nw, CS, 0, Yb, Nw, CS, 0,
             Pb, ldn, sh, ld4, 1.f, B2, Nw, CS, 0, -1.f, Nw, 1.f);
    };

    auto stats = [&](int rows, int F, const float* gam, const float* bet){
        k_bn_partial<<<CHUNKS, 256>>>(Yb, rows, F, Pt);
        k_bn_final<<<1, 256>>>(Pt, F, (float)rows, gam, bet, BNp);
    };
    auto elgrid = [](int total){ return (total + 255) / 256; };

    // ---- input transpose into e3a Xall X0 region (ld=32) ----
    k_transpose_in<<<elgrid(768*Bt*8), 256>>>(x, Xb, 768*Bt*8, 32);

    // ---- e3a: L3, 8 -> 32 (FFMA path) ----
    enc(0, 768, 8, 32, w_e3a);
    stats(196608, 32, g_e3a, b_e3a);
    k_bn_apply<<<elgrid(196608*32), 256>>>(Yb, BNp, Xb, 196608*32, 32, 128);

    // ---- e3b: L3, 32 -> 64 (HMMA BN=64) ----
    enc(0, 768, 32, 64, w_e3b);
    stats(196608, 64, g_e3b, b_e3b);
    k_bn_apply<<<elgrid(196608*64), 256>>>(Yb, BNp, S3, 196608*64, 64, 64);
    k_bn_pool<<<elgrid(192*Bt*64), 256>>>(Yb, BNp, Xb, 192*Bt*64, 64, Bt*64, 256);

    // ---- e2: L2, 64 -> 128 ----
    enc(1, 192, 64, 128, w_e2);
    stats(49152, 128, g_e2, b_e2);
    k_bn_apply<<<elgrid(49152*128), 256>>>(Yb, BNp, S2, 49152*128, 128, 128);
    k_bn_pool<<<elgrid(48*Bt*128), 256>>>(Yb, BNp, Xb, 48*Bt*128, 128, Bt*128, 512);

    // ---- e1: L1, 128 -> 256 ----
    enc(2, 48, 128, 256, w_e1);
    stats(12288, 256, g_e1, b_e1);
    k_bn_apply<<<elgrid(12288*256), 256>>>(Yb, BNp, S1, 12288*256, 256, 256);
    k_bn_pool<<<elgrid(12*Bt*256), 256>>>(Yb, BNp, Xb, 12*Bt*256, 256, Bt*256, 1024);

    // ---- e0: L0, 256 -> 256 ----
    enc(3, 12, 256, 256, w_e0);
    stats(3072, 256, g_e0, b_e0);
    k_bn_unpool_cat<<<elgrid(12288*256), 256>>>(Yb, BNp, Xb, 12288*256, 256, 512, Bt);
    k_copy_cat<<<elgrid(12288*256), 256>>>(S1, Xb, 12288*256, 256, 512, 256);

    // ---- d1: L1, 512 -> 128 ----
    dec(2, 48, 512, 128, w_d1);
    stats(12288, 128, g_d1, b_d1);
    k_bn_unpool_cat<<<elgrid(49152*128), 256>>>(Yb, BNp, Xb, 49152*128, 128, 256, Bt);
    k_copy_cat<<<elgrid(49152*128), 256>>>(S2, Xb, 49152*128, 128, 256, 128);

    // ---- d2: L2, 256 -> 64 ----
    dec(1, 192, 256, 64, w_d2);
    stats(49152, 64, g_d2, b_d2);
    k_bn_unpool_cat<<<elgrid(196608*64), 256>>>(Yb, BNp, Xb, 196608*64, 64, 128, Bt);
    k_copy_cat<<<elgrid(196608*64), 256>>>(S3, Xb, 196608*64, 64, 128, 64);

    // ---- d3: L3, 128 -> 32 ----
    dec(0, 768, 128, 32, w_d3);
    stats(196608, 32, g_d3, b_d3);
    k_bn_apply<<<elgrid(196608*32), 256>>>(Yb, BNp, Xb, 196608*32, 32, 32);

    // ---- out: L3, 32 -> 1 (FFMA path, no BN) ----
    dec(0, 768, 32, 1, w_out);

    // ---- output transpose -> (4,1,8,8,768) ----
    k_transpose_out<<<elgrid(196608), 256>>>(Yb, out);
}